// round 12
// baseline (speedup 1.0000x reference)
#include <cuda_runtime.h>
#include <cuda_fp16.h>
#include <cstdint>

// Problem constants (B=4096, E=512, H=512, SEQ=128)
#define BATCH 4096
#define EDIM  512
#define HDIM  512
#define GDIM  2048
#define SEQL  128
#define NH    (BATCH * HDIM)

// step pipeline config: CTA tile 256m x 32hc, K chunks of 64, 3 stages
#define KCHUNK   64
#define KITER    (HDIM / KCHUNK)       // 8
#define NSTAGE   3
#define ROWPITCH 72                    // halves per smem row (144B = 9x16B)
#define A_ARR_B  (256 * ROWPITCH * 2)  // 36864 B (256 rows)
#define B_ARR_B  (128 * ROWPITCH * 2)  // 18432 B (128 p-rows)
#define STAGE_B  (A_ARR_B + B_ARR_B)   // 55296 B
#define SMEM_STEP (NSTAGE * STAGE_B)   // 165888 B

// ---------------- device scratch (no allocation allowed) ----------------
__device__ __half g_xph[BATCH * GDIM];           // 16 MB, [m][hcol][gate] fp16
__device__ float g_c[2][NH];                     // 16 MB
__device__ __half g_h16[2][NH];                  // 8 MB
__device__ __half g_wp[GDIM * HDIM];             // 2 MB, packed [nb=16][p=128][k=512]
__device__ unsigned g_cnt[16 * 8];               // per-(mb, kchunk) completion counters

// ---------------- helpers ----------------
__device__ __forceinline__ float tanha(float x) {
    float y; asm("tanh.approx.f32 %0, %1;" : "=f"(y) : "f"(x)); return y;
}
__device__ __forceinline__ float siga(float x) {
    return fmaf(0.5f, tanha(0.5f * x), 0.5f);
}
__device__ __forceinline__ void ldsm4(unsigned r[4], const void* p) {
    unsigned a = (unsigned)__cvta_generic_to_shared(p);
    asm volatile("ldmatrix.sync.aligned.m8n8.x4.shared.b16 {%0,%1,%2,%3}, [%4];"
                 : "=r"(r[0]), "=r"(r[1]), "=r"(r[2]), "=r"(r[3]) : "r"(a));
}
__device__ __forceinline__ void mma16816(float d[4], const unsigned a[4],
                                         unsigned b0, unsigned b1) {
    asm volatile(
        "mma.sync.aligned.m16n8k16.row.col.f32.f16.f16.f32 "
        "{%0,%1,%2,%3}, {%4,%5,%6,%7}, {%8,%9}, {%0,%1,%2,%3};"
        : "+f"(d[0]), "+f"(d[1]), "+f"(d[2]), "+f"(d[3])
        : "r"(a[0]), "r"(a[1]), "r"(a[2]), "r"(a[3]), "r"(b0), "r"(b1));
}
__device__ __forceinline__ void cp16(uint32_t dst, const void* src) {
    asm volatile("cp.async.cg.shared.global [%0], [%1], 16;" :: "r"(dst), "l"(src) : "memory");
}
__device__ __forceinline__ void cp_commit() {
    asm volatile("cp.async.commit_group;" ::: "memory");
}
template <int N>
__device__ __forceinline__ void cp_wait() {
    asm volatile("cp.async.wait_group %0;" :: "n"(N) : "memory");
}

// ---------------- prep: W_hh -> packed fp16 ----------------
__global__ void prep_w_kernel(const float* __restrict__ w, __half* __restrict__ wp) {
    int t = blockIdx.x * blockDim.x + threadIdx.x;
    int row = t >> 6;
    int k0  = (t & 63) * 8;
    int g = row >> 9, hcol = row & 511;
    int nb = hcol >> 5, hc = hcol & 31;
    int p = g * 32 + hc;
    const float* src = w + (size_t)row * 512 + k0;
    __half v[8];
    #pragma unroll
    for (int i = 0; i < 8; ++i) v[i] = __float2half_rn(src[i]);
    *(uint4*)(wp + (size_t)nb * 128 * 512 + (size_t)p * 512 + k0) = *(const uint4*)v;
}

// ---------------- prep: h0 -> fp16 ----------------
__global__ void prep_h_kernel(const float* __restrict__ h0, __half* __restrict__ h16) {
    int t = blockIdx.x * blockDim.x + threadIdx.x;
    size_t base = (size_t)t * 8;
    __half v[8];
    #pragma unroll
    for (int i = 0; i < 8; ++i) v[i] = __float2half_rn(h0[base + i]);
    *(uint4*)(h16 + base) = *(const uint4*)v;
}

// =====================================================================
//  x-projection (one-time, fp32 SIMT) -> fp16 gate-interleaved output
// =====================================================================
#define XP_NT 256
__device__ __forceinline__ unsigned long long pack2(float x, float y) {
    unsigned long long r;
    asm("mov.b64 %0, {%1, %2};" : "=l"(r) : "f"(x), "f"(y));
    return r;
}
__device__ __forceinline__ void fma2(unsigned long long& acc, unsigned long long a, unsigned long long b) {
    asm("fma.rn.f32x2 %0, %1, %2, %0;" : "+l"(acc) : "l"(a), "l"(b));
}
__device__ __forceinline__ float2 unpack2(unsigned long long v) {
    float2 f;
    asm("mov.b64 {%0, %1}, %2;" : "=f"(f.x), "=f"(f.y) : "l"(v));
    return f;
}

__global__ void __launch_bounds__(XP_NT)
xproj_kernel(const float* __restrict__ x, const float* __restrict__ w_ih,
             const float* __restrict__ b_ih, const float* __restrict__ b_hh,
             __half* __restrict__ xph) {
    __shared__ float As[64][36];
    __shared__ float Bs[32][130];
    const int m0 = blockIdx.y * 64, n0 = blockIdx.x * 32;
    const int tid = threadIdx.x, ty = tid >> 4, tx = tid & 15;
    unsigned long long acc[4][4];
    #pragma unroll
    for (int r = 0; r < 4; ++r)
        #pragma unroll
        for (int g = 0; g < 4; ++g) acc[r][g] = 0ull;

    for (int kc = 0; kc < 512; kc += 32) {
        #pragma unroll
        for (int p = 0; p < 2; ++p) {
            int q = tid + p * XP_NT, m = q >> 3, kq = q & 7;
            *(float4*)(&As[m][kq * 4]) = *(const float4*)(x + (size_t)(m0 + m) * 512 + kc + kq * 4);
        }
        #pragma unroll
        for (int p = 0; p < 4; ++p) {
            int q = tid + p * XP_NT, n = q >> 3, kq = q & 7;
            int g = n >> 5, c = n & 31;
            float4 v = *(const float4*)(w_ih + (size_t)(g * 512 + n0 + c) * 512 + kc + kq * 4);
            Bs[kq * 4 + 0][n] = v.x; Bs[kq * 4 + 1][n] = v.y;
            Bs[kq * 4 + 2][n] = v.z; Bs[kq * 4 + 3][n] = v.w;
        }
        __syncthreads();
        #pragma unroll
        for (int k = 0; k < 32; ++k) {
            unsigned long long a2[4], b2[4];
            #pragma unroll
            for (int r = 0; r < 4; ++r) { float a = As[ty * 4 + r][k]; a2[r] = pack2(a, a); }
            #pragma unroll
            for (int g = 0; g < 4; ++g)
                b2[g] = *(const unsigned long long*)(&Bs[k][g * 32 + tx * 2]);
            #pragma unroll
            for (int r = 0; r < 4; ++r)
                #pragma unroll
                for (int g = 0; g < 4; ++g) fma2(acc[r][g], a2[r], b2[g]);
        }
        __syncthreads();
    }
    const int hcol = n0 + tx * 2;
    #pragma unroll
    for (int r = 0; r < 4; ++r) {
        int b = m0 + ty * 4 + r;
        __half* dst = xph + ((size_t)b * 512 + hcol) * 4;
        #pragma unroll
        for (int g = 0; g < 4; ++g) {
            int j = g * 512 + hcol;
            float2 v = unpack2(acc[r][g]);
            v.x += b_ih[j] + b_hh[j];
            v.y += b_ih[j + 1] + b_hh[j + 1];
            dst[g]     = __float2half_rn(v.x);
            dst[4 + g] = __float2half_rn(v.y);
        }
    }
}

// =====================================================================
//  Persistent LSTM: one CTA per (step, mb, nb) tile, 256m x 32hc tiles.
//  grid = (256, 128): blockIdx.x = mb*16 + nb, blockIdx.y = step.
//  Fine-grained per-K-chunk dependencies: cnt[mb][kt], target 2t.
//  Warp tile 64m x 16hc x 4 gates (128 accums); 1 CTA/SM.
// =====================================================================
__global__ void __launch_bounds__(256, 1)
lstm_mega(const __half* __restrict__ wpk,
          const __half* __restrict__ xph,
          __half* __restrict__ hbase,
          float* __restrict__ cbase,
          float* __restrict__ outh,
          float* __restrict__ outc,
          unsigned* __restrict__ cnt) {
    extern __shared__ __align__(16) unsigned char smc[];
    const uint32_t sb = (uint32_t)__cvta_generic_to_shared(smc);

    const int t    = blockIdx.y;
    const int nb   = blockIdx.x & 15;   // 32 hcols
    const int mb   = blockIdx.x >> 4;   // 256 batch rows
    const int tid  = threadIdx.x;
    const int lane = tid & 31;
    const int w    = tid >> 5;
    const int warp_m = (w >> 1) * 64;   // 4 m-groups of 64 rows
    const int hsl    = (w & 1) * 16;

    const __half* h_in  = hbase + (size_t)(t & 1) * NH;
    __half*       h_out = hbase + (size_t)((t + 1) & 1) * NH;
    const float*  c_in  = cbase + (size_t)(t & 1) * NH;
    float*        c_out = cbase + (size_t)((t + 1) & 1) * NH;

    const __half* Ag = h_in + (size_t)mb * 256 * 512;
    const __half* Bg = wpk + (size_t)nb * 128 * 512;

    const unsigned dep_target = 2u * (unsigned)t;
    volatile unsigned* depc = cnt + mb * 8;

    // per-chunk dependency spin (chunk kt needs producers (t-1, mb, 2kt/2kt+1))
    #define SPIN(KT) do {                                                      \
        if (dep_target && tid == 0) {                                          \
            while (depc[(KT)] < dep_target) __nanosleep(32);                   \
            __threadfence();                                                   \
        }                                                                      \
    } while (0)

    // ---- cp.async stage issue: A 2048 x 16B (256 rows), B 1024 x 16B ----
    #define ISSUE_A(KC, SLOT) do {                                             \
        uint32_t sb0_ = sb + (SLOT) * STAGE_B;                                 \
        _Pragma("unroll")                                                      \
        for (int i_ = 0; i_ < 8; ++i_) {                                       \
            int idx_ = tid + i_ * 256;                                         \
            int row_ = idx_ >> 3;                                              \
            int ch_  = idx_ & 7;                                               \
            cp16(sb0_ + row_ * (ROWPITCH * 2) + ch_ * 16,                      \
                 Ag + (size_t)row_ * 512 + (KC) * KCHUNK + ch_ * 8);           \
        }                                                                      \
    } while (0)
    #define ISSUE_B(KC, SLOT) do {                                             \
        uint32_t sb0_ = sb + (SLOT) * STAGE_B + A_ARR_B;                       \
        _Pragma("unroll")                                                      \
        for (int i_ = 0; i_ < 4; ++i_) {                                       \
            int idx_ = tid + i_ * 256;                                         \
            int row_ = idx_ >> 3;                                              \
            int ch_  = idx_ & 7;                                               \
            cp16(sb0_ + row_ * (ROWPITCH * 2) + ch_ * 16,                      \
                 Bg + (size_t)row_ * 512 + (KC) * KCHUNK + ch_ * 8);           \
        }                                                                      \
    } while (0)

    // B has no h dependency: issue before any spin.
    ISSUE_B(0, 0);
    ISSUE_B(1, 1);

    SPIN(0);
    __syncthreads();
    ISSUE_A(0, 0); cp_commit();      // group: B0,B1,A0
    SPIN(1);
    __syncthreads();
    ISSUE_A(1, 1); cp_commit();      // group: A1

    float d[4][4][2][4];
    #pragma unroll
    for (int a = 0; a < 4; ++a)
        #pragma unroll
        for (int b = 0; b < 4; ++b)
            #pragma unroll
            for (int c = 0; c < 2; ++c)
                #pragma unroll
                for (int e = 0; e < 4; ++e) d[a][b][c][e] = 0.0f;

    const int arow  = warp_m + (lane & 15);
    const int acolo = (lane >> 4) * 8;
    const int brow  = hsl + ((lane >> 4) << 3) + (lane & 7);
    const int bcolo = ((lane >> 3) & 1) * 8;

    for (int kc = 0; kc < KITER; ++kc) {
        cp_wait<1>();
        if (kc + 2 < KITER) SPIN(kc + 2);
        __syncthreads();
        if (kc + 2 < KITER) {
            ISSUE_A(kc + 2, (kc + 2) % NSTAGE);
            ISSUE_B(kc + 2, (kc + 2) % NSTAGE);
        }
        cp_commit();

        unsigned char* stg = smc + (kc % NSTAGE) * STAGE_B;
        __half (*Ah)[ROWPITCH] = (__half(*)[ROWPITCH])(stg);
        __half (*Bs)[ROWPITCH] = (__half(*)[ROWPITCH])(stg + A_ARR_B);

        #pragma unroll
        for (int kk = 0; kk < KCHUNK; kk += 16) {
            unsigned af[4][4];
            #pragma unroll
            for (int mt = 0; mt < 4; ++mt)
                ldsm4(af[mt], &Ah[arow + mt * 16][kk + acolo]);

            #pragma unroll
            for (int g = 0; g < 4; ++g) {
                unsigned bf[4];
                ldsm4(bf, &Bs[g * 32 + brow][kk + bcolo]);
                #pragma unroll
                for (int mt = 0; mt < 4; ++mt) {
                    mma16816(d[mt][g][0], af[mt], bf[0], bf[1]);
                    mma16816(d[mt][g][1], af[mt], bf[2], bf[3]);
                }
            }
        }
    }
    #undef ISSUE_A
    #undef ISSUE_B
    #undef SPIN

    // ---------- epilogue: thread-local gate fusion ----------
    const int gid = lane >> 2;
    const int tig = lane & 3;
    const bool last = (t == SEQL - 1);

    #pragma unroll
    for (int mt = 0; mt < 4; ++mt) {
        #pragma unroll
        for (int rh = 0; rh < 2; ++rh) {
            int m = mb * 256 + warp_m + mt * 16 + gid + rh * 8;
            #pragma unroll
            for (int j = 0; j < 2; ++j) {
                int hcol = nb * 32 + hsl + j * 8 + tig * 2;

                // one 16B load: [hcol: i,f,g,o | hcol+1: i,f,g,o] fp16
                uint4 pk = *(const uint4*)(xph + ((size_t)m * 512 + hcol) * 4);
                __half2* hp = (__half2*)&pk;
                float2 if0 = __half22float2(hp[0]);
                float2 go0 = __half22float2(hp[1]);
                float2 if1 = __half22float2(hp[2]);
                float2 go1 = __half22float2(hp[3]);

                float gix = if0.x + d[mt][0][j][rh * 2];
                float giy = if1.x + d[mt][0][j][rh * 2 + 1];
                float gfx = if0.y + d[mt][1][j][rh * 2];
                float gfy = if1.y + d[mt][1][j][rh * 2 + 1];
                float ggx = go0.x + d[mt][2][j][rh * 2];
                float ggy = go1.x + d[mt][2][j][rh * 2 + 1];
                float gox = go0.y + d[mt][3][j][rh * 2];
                float goy = go1.y + d[mt][3][j][rh * 2 + 1];

                float2 cv = *(const float2*)(c_in + (size_t)m * HDIM + hcol);

                float ix = siga(gix), iy = siga(giy);
                float fx = siga(gfx), fy = siga(gfy);
                float gx = tanha(ggx), gy = tanha(ggy);
                float ox = siga(gox), oy = siga(goy);

                float cnx = fmaf(fx, cv.x, ix * gx);
                float cny = fmaf(fy, cv.y, iy * gy);
                float hnx = ox * tanha(cnx);
                float hny = oy * tanha(cny);

                *(float2*)(c_out + (size_t)m * HDIM + hcol) = make_float2(cnx, cny);

                __half2 vh;
                vh.x = __float2half_rn(hnx);
                vh.y = __float2half_rn(hny);
                *(__half2*)(h_out + (size_t)m * HDIM + hcol) = vh;

                if (last) {
                    *(float2*)(outh + (size_t)m * HDIM + hcol) = make_float2(hnx, hny);
                    if (outc)
                        *(float2*)(outc + (size_t)m * HDIM + hcol) = make_float2(cnx, cny);
                }
            }
        }
    }

    // ---- signal: this (t, mb, nb) slice complete (kt = nb>>1) ----
    __threadfence();
    __syncthreads();
    if (tid == 0) atomicAdd((unsigned*)(cnt + mb * 8 + (nb >> 1)), 1u);
}

// =====================================================================
extern "C" void kernel_launch(void* const* d_in, const int* in_sizes, int n_in,
                              void* d_out, int out_size) {
    const float* start_emb = (const float*)d_in[0];
    const float* h0        = (const float*)d_in[1];
    const float* c0        = (const float*)d_in[2];
    const float* w_ih      = (const float*)d_in[3];
    const float* w_hh      = (const float*)d_in[4];
    const float* b_ih      = (const float*)d_in[5];
    const float* b_hh      = (const float*)d_in[6];
    float* out = (float*)d_out;

    float* cbuf;
    __half *xph, *hb, *wp;
    unsigned* cnt;
    cudaGetSymbolAddress((void**)&xph,  g_xph);
    cudaGetSymbolAddress((void**)&cbuf, g_c);
    cudaGetSymbolAddress((void**)&hb,   g_h16);
    cudaGetSymbolAddress((void**)&wp,   g_wp);
    cudaGetSymbolAddress((void**)&cnt,  g_cnt);

    cudaFuncSetAttribute(lstm_mega, cudaFuncAttributeMaxDynamicSharedMemorySize, SMEM_STEP);

    cudaMemsetAsync(cnt, 0, 16 * 8 * sizeof(unsigned), 0);
    cudaMemcpyAsync(cbuf, c0, (size_t)NH * sizeof(float), cudaMemcpyDeviceToDevice, 0);

    prep_w_kernel<<<(GDIM * 64) / 256, 256>>>(w_hh, wp);
    prep_h_kernel<<<(NH / 8) / 256, 256>>>(h0, hb);

    dim3 grid_xp(HDIM / 32, BATCH / 64);
    xproj_kernel<<<grid_xp, XP_NT>>>(start_emb, w_ih, b_ih, b_hh, xph);

    const bool out_has_c = (out_size >= 2 * NH);
    float* outc = out_has_c ? (out + NH) : nullptr;

    dim3 grid_mega(256, SEQL);   // (tile: mb*16+nb with 256-row mb, step)
    lstm_mega<<<grid_mega, 256, SMEM_STEP>>>(wp, xph, hb, cbuf, out, outc, cnt);
}

// round 13
// speedup vs baseline: 1.1943x; 1.1943x over previous
#include <cuda_runtime.h>
#include <cuda_fp16.h>
#include <cstdint>

// Problem constants (B=4096, E=512, H=512, SEQ=128)
#define BATCH 4096
#define EDIM  512
#define HDIM  512
#define GDIM  2048
#define SEQL  128
#define NH    (BATCH * HDIM)

// step pipeline config: K chunks of 64, 3 stages
#define KCHUNK   64
#define KITER    (HDIM / KCHUNK)       // 8
#define NSTAGE   3
#define ROWPITCH 72                    // halves per smem row (144B = 9x16B)
#define ARR_B    (128 * ROWPITCH * 2)  // 18432 B per array
#define STAGE_B  (2 * ARR_B)           // A + B = 36864 B
#define SMEM_STEP (NSTAGE * STAGE_B)   // 110592 B

// ---------------- device scratch (no allocation allowed) ----------------
__device__ __half g_xph[BATCH * GDIM];           // 16 MB, [m][hcol][gate] fp16
__device__ float g_c[2][NH];                     // 16 MB
__device__ __half g_h16[2][NH];                  // 8 MB
__device__ __half g_wp[GDIM * HDIM];             // 2 MB, packed [nb=16][p=128][k=512]
__device__ unsigned g_cnt[32 * 8];               // per-(mb, kchunk) completion counters

// ---------------- helpers ----------------
__device__ __forceinline__ float tanha(float x) {
    float y; asm("tanh.approx.f32 %0, %1;" : "=f"(y) : "f"(x)); return y;
}
__device__ __forceinline__ float siga(float x) {
    return fmaf(0.5f, tanha(0.5f * x), 0.5f);
}
__device__ __forceinline__ void ldsm4(unsigned r[4], const void* p) {
    unsigned a = (unsigned)__cvta_generic_to_shared(p);
    asm volatile("ldmatrix.sync.aligned.m8n8.x4.shared.b16 {%0,%1,%2,%3}, [%4];"
                 : "=r"(r[0]), "=r"(r[1]), "=r"(r[2]), "=r"(r[3]) : "r"(a));
}
__device__ __forceinline__ void mma16816(float d[4], const unsigned a[4],
                                         unsigned b0, unsigned b1) {
    asm volatile(
        "mma.sync.aligned.m16n8k16.row.col.f32.f16.f16.f32 "
        "{%0,%1,%2,%3}, {%4,%5,%6,%7}, {%8,%9}, {%0,%1,%2,%3};"
        : "+f"(d[0]), "+f"(d[1]), "+f"(d[2]), "+f"(d[3])
        : "r"(a[0]), "r"(a[1]), "r"(a[2]), "r"(a[3]), "r"(b0), "r"(b1));
}
__device__ __forceinline__ void cp16(uint32_t dst, const void* src) {
    asm volatile("cp.async.cg.shared.global [%0], [%1], 16;" :: "r"(dst), "l"(src) : "memory");
}
__device__ __forceinline__ void cp_commit() {
    asm volatile("cp.async.commit_group;" ::: "memory");
}
template <int N>
__device__ __forceinline__ void cp_wait() {
    asm volatile("cp.async.wait_group %0;" :: "n"(N) : "memory");
}

// ---------------- prep: W_hh -> packed fp16 ----------------
__global__ void prep_w_kernel(const float* __restrict__ w, __half* __restrict__ wp) {
    int t = blockIdx.x * blockDim.x + threadIdx.x;
    int row = t >> 6;
    int k0  = (t & 63) * 8;
    int g = row >> 9, hcol = row & 511;
    int nb = hcol >> 5, hc = hcol & 31;
    int p = g * 32 + hc;
    const float* src = w + (size_t)row * 512 + k0;
    __half v[8];
    #pragma unroll
    for (int i = 0; i < 8; ++i) v[i] = __float2half_rn(src[i]);
    *(uint4*)(wp + (size_t)nb * 128 * 512 + (size_t)p * 512 + k0) = *(const uint4*)v;
}

// ---------------- prep: h0 -> fp16 ----------------
__global__ void prep_h_kernel(const float* __restrict__ h0, __half* __restrict__ h16) {
    int t = blockIdx.x * blockDim.x + threadIdx.x;
    size_t base = (size_t)t * 8;
    __half v[8];
    #pragma unroll
    for (int i = 0; i < 8; ++i) v[i] = __float2half_rn(h0[base + i]);
    *(uint4*)(h16 + base) = *(const uint4*)v;
}

// =====================================================================
//  x-projection (one-time, fp32 SIMT) -> fp16 gate-interleaved output
// =====================================================================
#define XP_NT 256
__device__ __forceinline__ unsigned long long pack2(float x, float y) {
    unsigned long long r;
    asm("mov.b64 %0, {%1, %2};" : "=l"(r) : "f"(x), "f"(y));
    return r;
}
__device__ __forceinline__ void fma2(unsigned long long& acc, unsigned long long a, unsigned long long b) {
    asm("fma.rn.f32x2 %0, %1, %2, %0;" : "+l"(acc) : "l"(a), "l"(b));
}
__device__ __forceinline__ float2 unpack2(unsigned long long v) {
    float2 f;
    asm("mov.b64 {%0, %1}, %2;" : "=f"(f.x), "=f"(f.y) : "l"(v));
    return f;
}

__global__ void __launch_bounds__(XP_NT)
xproj_kernel(const float* __restrict__ x, const float* __restrict__ w_ih,
             const float* __restrict__ b_ih, const float* __restrict__ b_hh,
             __half* __restrict__ xph) {
    __shared__ float As[64][36];
    __shared__ float Bs[32][130];
    const int m0 = blockIdx.y * 64, n0 = blockIdx.x * 32;
    const int tid = threadIdx.x, ty = tid >> 4, tx = tid & 15;
    unsigned long long acc[4][4];
    #pragma unroll
    for (int r = 0; r < 4; ++r)
        #pragma unroll
        for (int g = 0; g < 4; ++g) acc[r][g] = 0ull;

    for (int kc = 0; kc < 512; kc += 32) {
        #pragma unroll
        for (int p = 0; p < 2; ++p) {
            int q = tid + p * XP_NT, m = q >> 3, kq = q & 7;
            *(float4*)(&As[m][kq * 4]) = *(const float4*)(x + (size_t)(m0 + m) * 512 + kc + kq * 4);
        }
        #pragma unroll
        for (int p = 0; p < 4; ++p) {
            int q = tid + p * XP_NT, n = q >> 3, kq = q & 7;
            int g = n >> 5, c = n & 31;
            float4 v = *(const float4*)(w_ih + (size_t)(g * 512 + n0 + c) * 512 + kc + kq * 4);
            Bs[kq * 4 + 0][n] = v.x; Bs[kq * 4 + 1][n] = v.y;
            Bs[kq * 4 + 2][n] = v.z; Bs[kq * 4 + 3][n] = v.w;
        }
        __syncthreads();
        #pragma unroll
        for (int k = 0; k < 32; ++k) {
            unsigned long long a2[4], b2[4];
            #pragma unroll
            for (int r = 0; r < 4; ++r) { float a = As[ty * 4 + r][k]; a2[r] = pack2(a, a); }
            #pragma unroll
            for (int g = 0; g < 4; ++g)
                b2[g] = *(const unsigned long long*)(&Bs[k][g * 32 + tx * 2]);
            #pragma unroll
            for (int r = 0; r < 4; ++r)
                #pragma unroll
                for (int g = 0; g < 4; ++g) fma2(acc[r][g], a2[r], b2[g]);
        }
        __syncthreads();
    }
    const int hcol = n0 + tx * 2;
    #pragma unroll
    for (int r = 0; r < 4; ++r) {
        int b = m0 + ty * 4 + r;
        __half* dst = xph + ((size_t)b * 512 + hcol) * 4;
        #pragma unroll
        for (int g = 0; g < 4; ++g) {
            int j = g * 512 + hcol;
            float2 v = unpack2(acc[r][g]);
            v.x += b_ih[j] + b_hh[j];
            v.y += b_ih[j + 1] + b_hh[j + 1];
            dst[g]     = __float2half_rn(v.x);
            dst[4 + g] = __float2half_rn(v.y);
        }
    }
}

// =====================================================================
//  Persistent LSTM: one CTA per (step, mb, nb) tile (R10 geometry).
//  grid = (512, 128): blockIdx.x = mb*16 + nb, blockIdx.y = step.
//  Fine-grained per-K-chunk dependencies: cnt[mb][kt] >= 2t, where
//  chunk kt's A columns are written by producers (t-1, mb, 2kt/2kt+1).
// =====================================================================
__global__ void __launch_bounds__(256, 2)
lstm_mega(const __half* __restrict__ wpk,
          const __half* __restrict__ xph,
          __half* __restrict__ hbase,
          float* __restrict__ cbase,
          float* __restrict__ outh,
          float* __restrict__ outc,
          unsigned* __restrict__ cnt) {
    extern __shared__ __align__(16) unsigned char smc[];
    const uint32_t sb = (uint32_t)__cvta_generic_to_shared(smc);

    const int t    = blockIdx.y;
    const int nb   = blockIdx.x & 15;   // 32 hcols
    const int mb   = blockIdx.x >> 4;   // 128 batch rows
    const int tid  = threadIdx.x;
    const int lane = tid & 31;
    const int w    = tid >> 5;
    const int warp_m = (w >> 1) * 32;
    const int hsl    = (w & 1) * 16;

    const __half* h_in  = hbase + (size_t)(t & 1) * NH;
    __half*       h_out = hbase + (size_t)((t + 1) & 1) * NH;
    const float*  c_in  = cbase + (size_t)(t & 1) * NH;
    float*        c_out = cbase + (size_t)((t + 1) & 1) * NH;

    const __half* Ag = h_in + (size_t)mb * 128 * 512;
    const __half* Bg = wpk + (size_t)nb * 128 * 512;

    const unsigned dep_target = 2u * (unsigned)t;
    volatile unsigned* depc = cnt + mb * 8;

    // per-chunk dependency spin: chunk kt needs producers (t-1, mb, 2kt/2kt+1)
    #define SPIN(KT) do {                                                      \
        if (dep_target && tid == 0) {                                          \
            while (depc[(KT)] < dep_target) __nanosleep(32);                   \
            __threadfence();                                                   \
        }                                                                      \
    } while (0)

    // ---- cp.async stage issue, split A (h rows) / B (weights) ----
    #define ISSUE_A(KC, SLOT) do {                                             \
        uint32_t sb0_ = sb + (SLOT) * STAGE_B;                                 \
        _Pragma("unroll")                                                      \
        for (int i_ = 0; i_ < 4; ++i_) {                                       \
            int idx_ = tid + i_ * 256;                                         \
            int row_ = idx_ >> 3;                                              \
            int ch_  = idx_ & 7;                                               \
            cp16(sb0_ + row_ * (ROWPITCH * 2) + ch_ * 16,                      \
                 Ag + (size_t)row_ * 512 + (KC) * KCHUNK + ch_ * 8);           \
        }                                                                      \
    } while (0)
    #define ISSUE_B(KC, SLOT) do {                                             \
        uint32_t sb0_ = sb + (SLOT) * STAGE_B + ARR_B;                         \
        _Pragma("unroll")                                                      \
        for (int i_ = 0; i_ < 4; ++i_) {                                       \
            int idx_ = tid + i_ * 256;                                         \
            int row_ = idx_ >> 3;                                              \
            int ch_  = idx_ & 7;                                               \
            cp16(sb0_ + row_ * (ROWPITCH * 2) + ch_ * 16,                      \
                 Bg + (size_t)row_ * 512 + (KC) * KCHUNK + ch_ * 8);           \
        }                                                                      \
    } while (0)

    // B has no h dependency: issue before any spin.
    ISSUE_B(0, 0);
    ISSUE_B(1, 1);

    SPIN(0);
    ISSUE_A(0, 0); cp_commit();      // group: B0,B1,A0
    SPIN(1);
    ISSUE_A(1, 1); cp_commit();      // group: A1

    float d[2][4][2][4];
    #pragma unroll
    for (int a = 0; a < 2; ++a)
        #pragma unroll
        for (int b = 0; b < 4; ++b)
            #pragma unroll
            for (int c = 0; c < 2; ++c)
                #pragma unroll
                for (int e = 0; e < 4; ++e) d[a][b][c][e] = 0.0f;

    const int arow  = warp_m + (lane & 15);
    const int acolo = (lane >> 4) * 8;
    const int brow  = hsl + ((lane >> 4) << 3) + (lane & 7);
    const int bcolo = ((lane >> 3) & 1) * 8;

    for (int kc = 0; kc < KITER; ++kc) {
        cp_wait<1>();
        if (kc + 2 < KITER) SPIN(kc + 2);
        __syncthreads();
        if (kc + 2 < KITER) {
            ISSUE_A(kc + 2, (kc + 2) % NSTAGE);
            ISSUE_B(kc + 2, (kc + 2) % NSTAGE);
        }
        cp_commit();

        unsigned char* stg = smc + (kc % NSTAGE) * STAGE_B;
        __half (*Ah)[ROWPITCH] = (__half(*)[ROWPITCH])(stg);
        __half (*Bs)[ROWPITCH] = (__half(*)[ROWPITCH])(stg + ARR_B);

        #pragma unroll
        for (int kk = 0; kk < KCHUNK; kk += 16) {
            unsigned af[2][4];
            ldsm4(af[0], &Ah[arow][kk + acolo]);
            ldsm4(af[1], &Ah[arow + 16][kk + acolo]);

            #pragma unroll
            for (int g = 0; g < 4; ++g) {
                unsigned bf[4];
                ldsm4(bf, &Bs[g * 32 + brow][kk + bcolo]);
                #pragma unroll
                for (int mt = 0; mt < 2; ++mt) {
                    mma16816(d[mt][g][0], af[mt], bf[0], bf[1]);
                    mma16816(d[mt][g][1], af[mt], bf[2], bf[3]);
                }
            }
        }
    }
    #undef ISSUE_A
    #undef ISSUE_B
    #undef SPIN

    // ---------- epilogue: thread-local gate fusion ----------
    const int gid = lane >> 2;
    const int tig = lane & 3;
    const bool last = (t == SEQL - 1);

    #pragma unroll
    for (int mt = 0; mt < 2; ++mt) {
        #pragma unroll
        for (int rh = 0; rh < 2; ++rh) {
            int m = mb * 128 + warp_m + mt * 16 + gid + rh * 8;
            #pragma unroll
            for (int j = 0; j < 2; ++j) {
                int hcol = nb * 32 + hsl + j * 8 + tig * 2;

                // one 16B load: [hcol: i,f,g,o | hcol+1: i,f,g,o] fp16
                uint4 pk = *(const uint4*)(xph + ((size_t)m * 512 + hcol) * 4);
                __half2* hp = (__half2*)&pk;
                float2 if0 = __half22float2(hp[0]);
                float2 go0 = __half22float2(hp[1]);
                float2 if1 = __half22float2(hp[2]);
                float2 go1 = __half22float2(hp[3]);

                float gix = if0.x + d[mt][0][j][rh * 2];
                float giy = if1.x + d[mt][0][j][rh * 2 + 1];
                float gfx = if0.y + d[mt][1][j][rh * 2];
                float gfy = if1.y + d[mt][1][j][rh * 2 + 1];
                float ggx = go0.x + d[mt][2][j][rh * 2];
                float ggy = go1.x + d[mt][2][j][rh * 2 + 1];
                float gox = go0.y + d[mt][3][j][rh * 2];
                float goy = go1.y + d[mt][3][j][rh * 2 + 1];

                float2 cv = *(const float2*)(c_in + (size_t)m * HDIM + hcol);

                float ix = siga(gix), iy = siga(giy);
                float fx = siga(gfx), fy = siga(gfy);
                float gx = tanha(ggx), gy = tanha(ggy);
                float ox = siga(gox), oy = siga(goy);

                float cnx = fmaf(fx, cv.x, ix * gx);
                float cny = fmaf(fy, cv.y, iy * gy);
                float hnx = ox * tanha(cnx);
                float hny = oy * tanha(cny);

                *(float2*)(c_out + (size_t)m * HDIM + hcol) = make_float2(cnx, cny);

                __half2 vh;
                vh.x = __float2half_rn(hnx);
                vh.y = __float2half_rn(hny);
                *(__half2*)(h_out + (size_t)m * HDIM + hcol) = vh;

                if (last) {
                    *(float2*)(outh + (size_t)m * HDIM + hcol) = make_float2(hnx, hny);
                    if (outc)
                        *(float2*)(outc + (size_t)m * HDIM + hcol) = make_float2(cnx, cny);
                }
            }
        }
    }

    // ---- signal: this (t, mb, nb) slice complete (chunk kt = nb>>1) ----
    __threadfence();
    __syncthreads();
    if (tid == 0) atomicAdd((unsigned*)(cnt + mb * 8 + (nb >> 1)), 1u);
}

// =====================================================================
extern "C" void kernel_launch(void* const* d_in, const int* in_sizes, int n_in,
                              void* d_out, int out_size) {
    const float* start_emb = (const float*)d_in[0];
    const float* h0        = (const float*)d_in[1];
    const float* c0        = (const float*)d_in[2];
    const float* w_ih      = (const float*)d_in[3];
    const float* w_hh      = (const float*)d_in[4];
    const float* b_ih      = (const float*)d_in[5];
    const float* b_hh      = (const float*)d_in[6];
    float* out = (float*)d_out;

    float* cbuf;
    __half *xph, *hb, *wp;
    unsigned* cnt;
    cudaGetSymbolAddress((void**)&xph,  g_xph);
    cudaGetSymbolAddress((void**)&cbuf, g_c);
    cudaGetSymbolAddress((void**)&hb,   g_h16);
    cudaGetSymbolAddress((void**)&wp,   g_wp);
    cudaGetSymbolAddress((void**)&cnt,  g_cnt);

    cudaFuncSetAttribute(lstm_mega, cudaFuncAttributeMaxDynamicSharedMemorySize, SMEM_STEP);

    cudaMemsetAsync(cnt, 0, 32 * 8 * sizeof(unsigned), 0);
    cudaMemcpyAsync(cbuf, c0, (size_t)NH * sizeof(float), cudaMemcpyDeviceToDevice, 0);

    prep_w_kernel<<<(GDIM * 64) / 256, 256>>>(w_hh, wp);
    prep_h_kernel<<<(NH / 8) / 256, 256>>>(h0, hb);

    dim3 grid_xp(HDIM / 32, BATCH / 64);
    xproj_kernel<<<grid_xp, XP_NT>>>(start_emb, w_ih, b_ih, b_hh, xph);

    const bool out_has_c = (out_size >= 2 * NH);
    float* outc = out_has_c ? (out + NH) : nullptr;

    dim3 grid_mega(512, SEQL);   // (tile: mb*16+nb, step)
    lstm_mega<<<grid_mega, 256, SMEM_STEP>>>(wp, xph, hb, cbuf, out, outc, cnt);
}

// round 15
// speedup vs baseline: 1.7411x; 1.4579x over previous
#include <cuda_runtime.h>
#include <cuda_fp16.h>
#include <cstdint>

// Problem constants (B=4096, E=512, H=512, SEQ=128)
#define BATCH 4096
#define EDIM  512
#define HDIM  512
#define GDIM  2048
#define SEQL  128
#define NH    (BATCH * HDIM)

// step pipeline config: K chunks of 64, 3 slots, mbarrier ring
#define KCHUNK   64
#define KITER    (HDIM / KCHUNK)       // 8
#define NSTAGE   3
#define ROWPITCH 72                    // halves per smem row (144B = 9x16B)
#define ARR_B    (128 * ROWPITCH * 2)  // 18432 B per array
#define STAGE_B  (2 * ARR_B)           // A + B = 36864 B
#define SMEM_STEP (NSTAGE * STAGE_B + 64)   // +64 for mbarriers

// ---------------- device scratch (no allocation allowed) ----------------
__device__ __half g_xph[BATCH * GDIM];           // 16 MB, [m][hcol][gate] fp16
__device__ float g_c[2][NH];                     // 16 MB
__device__ __half g_h16[2][NH];                  // 8 MB
__device__ __half g_wp[GDIM * HDIM];             // 2 MB, packed [nb=16][p=128][k=512]
__device__ unsigned g_cnt[32];                   // per-mb step completion counters

// ---------------- helpers ----------------
__device__ __forceinline__ float tanha(float x) {
    float y; asm("tanh.approx.f32 %0, %1;" : "=f"(y) : "f"(x)); return y;
}
__device__ __forceinline__ float siga(float x) {
    return fmaf(0.5f, tanha(0.5f * x), 0.5f);
}
__device__ __forceinline__ void ldsm4(unsigned r[4], const void* p) {
    unsigned a = (unsigned)__cvta_generic_to_shared(p);
    asm volatile("ldmatrix.sync.aligned.m8n8.x4.shared.b16 {%0,%1,%2,%3}, [%4];"
                 : "=r"(r[0]), "=r"(r[1]), "=r"(r[2]), "=r"(r[3]) : "r"(a));
}
__device__ __forceinline__ void mma16816(float d[4], const unsigned a[4],
                                         unsigned b0, unsigned b1) {
    asm volatile(
        "mma.sync.aligned.m16n8k16.row.col.f32.f16.f16.f32 "
        "{%0,%1,%2,%3}, {%4,%5,%6,%7}, {%8,%9}, {%0,%1,%2,%3};"
        : "+f"(d[0]), "+f"(d[1]), "+f"(d[2]), "+f"(d[3])
        : "r"(a[0]), "r"(a[1]), "r"(a[2]), "r"(a[3]), "r"(b0), "r"(b1));
}
__device__ __forceinline__ void cp16(uint32_t dst, const void* src) {
    asm volatile("cp.async.cg.shared.global [%0], [%1], 16;" :: "r"(dst), "l"(src) : "memory");
}

// ---------------- mbarrier ops ----------------
#define MBAR_INIT(a, n) \
    asm volatile("mbarrier.init.shared.b64 [%0], %1;" :: "r"(a), "r"(n) : "memory")
#define MBAR_ARRIVE(a) \
    asm volatile("mbarrier.arrive.shared.b64 _, [%0];" :: "r"(a) : "memory")
// .noinc: arrive-on fires at completion of this thread's prior cp.asyncs
// WITHOUT incrementing the pending count at issue — the init count (256)
// already accounts for these arrivals. (Non-.noinc here deadlocks: R14.)
#define CP_MBAR_ARRIVE(a) \
    asm volatile("cp.async.mbarrier.arrive.noinc.shared::cta.b64 [%0];" :: "r"(a) : "memory")
#define MBAR_WAIT(a, ph) do {                                                   \
    asm volatile(                                                               \
        "{\n\t.reg .pred P1;\n\t"                                               \
        "WL_%=:\n\t"                                                            \
        "mbarrier.try_wait.parity.acquire.cta.shared::cta.b64 P1, [%0], %1, 0x989680;\n\t" \
        "@P1 bra.uni WD_%=;\n\t"                                                \
        "bra.uni WL_%=;\n\t"                                                    \
        "WD_%=:\n\t}"                                                           \
        :: "r"(a), "r"(ph) : "memory");                                         \
} while (0)

// ---------------- prep: W_hh -> packed fp16 ----------------
__global__ void prep_w_kernel(const float* __restrict__ w, __half* __restrict__ wp) {
    int t = blockIdx.x * blockDim.x + threadIdx.x;
    int row = t >> 6;
    int k0  = (t & 63) * 8;
    int g = row >> 9, hcol = row & 511;
    int nb = hcol >> 5, hc = hcol & 31;
    int p = g * 32 + hc;
    const float* src = w + (size_t)row * 512 + k0;
    __half v[8];
    #pragma unroll
    for (int i = 0; i < 8; ++i) v[i] = __float2half_rn(src[i]);
    *(uint4*)(wp + (size_t)nb * 128 * 512 + (size_t)p * 512 + k0) = *(const uint4*)v;
}

// ---------------- prep: h0 -> fp16 ----------------
__global__ void prep_h_kernel(const float* __restrict__ h0, __half* __restrict__ h16) {
    int t = blockIdx.x * blockDim.x + threadIdx.x;
    size_t base = (size_t)t * 8;
    __half v[8];
    #pragma unroll
    for (int i = 0; i < 8; ++i) v[i] = __float2half_rn(h0[base + i]);
    *(uint4*)(h16 + base) = *(const uint4*)v;
}

// =====================================================================
//  x-projection (one-time, fp32 SIMT) -> fp16 gate-interleaved output
// =====================================================================
#define XP_NT 256
__device__ __forceinline__ unsigned long long pack2(float x, float y) {
    unsigned long long r;
    asm("mov.b64 %0, {%1, %2};" : "=l"(r) : "f"(x), "f"(y));
    return r;
}
__device__ __forceinline__ void fma2(unsigned long long& acc, unsigned long long a, unsigned long long b) {
    asm("fma.rn.f32x2 %0, %1, %2, %0;" : "+l"(acc) : "l"(a), "l"(b));
}
__device__ __forceinline__ float2 unpack2(unsigned long long v) {
    float2 f;
    asm("mov.b64 {%0, %1}, %2;" : "=f"(f.x), "=f"(f.y) : "l"(v));
    return f;
}

__global__ void __launch_bounds__(XP_NT)
xproj_kernel(const float* __restrict__ x, const float* __restrict__ w_ih,
             const float* __restrict__ b_ih, const float* __restrict__ b_hh,
             __half* __restrict__ xph) {
    __shared__ float As[64][36];
    __shared__ float Bs[32][130];
    const int m0 = blockIdx.y * 64, n0 = blockIdx.x * 32;
    const int tid = threadIdx.x, ty = tid >> 4, tx = tid & 15;
    unsigned long long acc[4][4];
    #pragma unroll
    for (int r = 0; r < 4; ++r)
        #pragma unroll
        for (int g = 0; g < 4; ++g) acc[r][g] = 0ull;

    for (int kc = 0; kc < 512; kc += 32) {
        #pragma unroll
        for (int p = 0; p < 2; ++p) {
            int q = tid + p * XP_NT, m = q >> 3, kq = q & 7;
            *(float4*)(&As[m][kq * 4]) = *(const float4*)(x + (size_t)(m0 + m) * 512 + kc + kq * 4);
        }
        #pragma unroll
        for (int p = 0; p < 4; ++p) {
            int q = tid + p * XP_NT, n = q >> 3, kq = q & 7;
            int g = n >> 5, c = n & 31;
            float4 v = *(const float4*)(w_ih + (size_t)(g * 512 + n0 + c) * 512 + kc + kq * 4);
            Bs[kq * 4 + 0][n] = v.x; Bs[kq * 4 + 1][n] = v.y;
            Bs[kq * 4 + 2][n] = v.z; Bs[kq * 4 + 3][n] = v.w;
        }
        __syncthreads();
        #pragma unroll
        for (int k = 0; k < 32; ++k) {
            unsigned long long a2[4], b2[4];
            #pragma unroll
            for (int r = 0; r < 4; ++r) { float a = As[ty * 4 + r][k]; a2[r] = pack2(a, a); }
            #pragma unroll
            for (int g = 0; g < 4; ++g)
                b2[g] = *(const unsigned long long*)(&Bs[k][g * 32 + tx * 2]);
            #pragma unroll
            for (int r = 0; r < 4; ++r)
                #pragma unroll
                for (int g = 0; g < 4; ++g) fma2(acc[r][g], a2[r], b2[g]);
        }
        __syncthreads();
    }
    const int hcol = n0 + tx * 2;
    #pragma unroll
    for (int r = 0; r < 4; ++r) {
        int b = m0 + ty * 4 + r;
        __half* dst = xph + ((size_t)b * 512 + hcol) * 4;
        #pragma unroll
        for (int g = 0; g < 4; ++g) {
            int j = g * 512 + hcol;
            float2 v = unpack2(acc[r][g]);
            v.x += b_ih[j] + b_hh[j];
            v.y += b_ih[j + 1] + b_hh[j + 1];
            dst[g]     = __float2half_rn(v.x);
            dst[4 + g] = __float2half_rn(v.y);
        }
    }
}

// =====================================================================
//  Persistent LSTM: one CTA per (step, mb, nb) tile (R10 geometry).
//  grid = (512, 128): blockIdx.x = mb*16 + nb, blockIdx.y = step.
//  Coarse per-mb dependency spin (R10); mainloop synchronized with a
//  3-slot mbarrier ring (full: cp.async .noinc completion x256;
//  empty: 8 warp arrivals) — warps may skew across chunks.
// =====================================================================
__global__ void __launch_bounds__(256, 2)
lstm_mega(const __half* __restrict__ wpk,
          const __half* __restrict__ xph,
          __half* __restrict__ hbase,
          float* __restrict__ cbase,
          float* __restrict__ outh,
          float* __restrict__ outc,
          unsigned* __restrict__ cnt) {
    extern __shared__ __align__(16) unsigned char smc[];
    const uint32_t sb = (uint32_t)__cvta_generic_to_shared(smc);
    const uint32_t MB = sb + NSTAGE * STAGE_B;    // mbarriers: [full,empty] x 3

    const int t    = blockIdx.y;
    const int nb   = blockIdx.x & 15;   // 32 hcols
    const int mb   = blockIdx.x >> 4;   // 128 batch rows
    const int tid  = threadIdx.x;
    const int lane = tid & 31;
    const int w    = tid >> 5;
    const int warp_m = (w >> 1) * 32;
    const int hsl    = (w & 1) * 16;

    const __half* h_in  = hbase + (size_t)(t & 1) * NH;
    __half*       h_out = hbase + (size_t)((t + 1) & 1) * NH;
    const float*  c_in  = cbase + (size_t)(t & 1) * NH;
    float*        c_out = cbase + (size_t)((t + 1) & 1) * NH;

    const __half* Ag = h_in + (size_t)mb * 128 * 512;
    const __half* Bg = wpk + (size_t)nb * 128 * 512;

    // ---- mbarrier init ----
    if (tid == 0) {
        #pragma unroll
        for (int s = 0; s < NSTAGE; ++s) {
            MBAR_INIT(MB + s * 16, 256);       // full[s]: one .noinc arrival/thread
            MBAR_INIT(MB + s * 16 + 8, 8);     // empty[s]: one arrive per warp
        }
    }
    __syncthreads();

    // ---- cp.async stage issue, split A (h rows) / B (weights) ----
    #define ISSUE_A(KC, SLOT) do {                                             \
        uint32_t sb0_ = sb + (SLOT) * STAGE_B;                                 \
        _Pragma("unroll")                                                      \
        for (int i_ = 0; i_ < 4; ++i_) {                                       \
            int idx_ = tid + i_ * 256;                                         \
            int row_ = idx_ >> 3;                                              \
            int ch_  = idx_ & 7;                                               \
            cp16(sb0_ + row_ * (ROWPITCH * 2) + ch_ * 16,                      \
                 Ag + (size_t)row_ * 512 + (KC) * KCHUNK + ch_ * 8);           \
        }                                                                      \
    } while (0)
    #define ISSUE_B(KC, SLOT) do {                                             \
        uint32_t sb0_ = sb + (SLOT) * STAGE_B + ARR_B;                         \
        _Pragma("unroll")                                                      \
        for (int i_ = 0; i_ < 4; ++i_) {                                       \
            int idx_ = tid + i_ * 256;                                         \
            int row_ = idx_ >> 3;                                              \
            int ch_  = idx_ & 7;                                               \
            cp16(sb0_ + row_ * (ROWPITCH * 2) + ch_ * 16,                      \
                 Bg + (size_t)row_ * 512 + (KC) * KCHUNK + ch_ * 8);           \
        }                                                                      \
    } while (0)

    // B has no h dependency: fetch under the dependency wait.
    ISSUE_B(0, 0);
    ISSUE_B(1, 1);

    // ---- coarse wait: all 16 producers of (t-1, mb) ----
    if (t > 0) {
        if (tid == 0) {
            const unsigned target = 16u * (unsigned)t;
            volatile unsigned* p = cnt + mb;
            while (*p < target) __nanosleep(64);
            __threadfence();
        }
        __syncthreads();
    }

    ISSUE_A(0, 0); CP_MBAR_ARRIVE(MB + 0 * 16);   // full[0] <- B0,B1,A0 complete
    ISSUE_A(1, 1); CP_MBAR_ARRIVE(MB + 1 * 16);   // full[1] <- +A1 complete

    float d[2][4][2][4];
    #pragma unroll
    for (int a = 0; a < 2; ++a)
        #pragma unroll
        for (int b = 0; b < 4; ++b)
            #pragma unroll
            for (int c = 0; c < 2; ++c)
                #pragma unroll
                for (int e = 0; e < 4; ++e) d[a][b][c][e] = 0.0f;

    const int arow  = warp_m + (lane & 15);
    const int acolo = (lane >> 4) * 8;
    const int brow  = hsl + ((lane >> 4) << 3) + (lane & 7);
    const int bcolo = ((lane >> 3) & 1) * 8;

    #pragma unroll
    for (int kc = 0; kc < KITER; ++kc) {
        const int scur = kc % NSTAGE;
        MBAR_WAIT(MB + scur * 16, (kc / NSTAGE) & 1);

        unsigned char* stg = smc + scur * STAGE_B;
        __half (*Ah)[ROWPITCH] = (__half(*)[ROWPITCH])(stg);
        __half (*Bs)[ROWPITCH] = (__half(*)[ROWPITCH])(stg + ARR_B);

        #pragma unroll
        for (int kk = 0; kk < KCHUNK; kk += 16) {
            unsigned af[2][4];
            ldsm4(af[0], &Ah[arow][kk + acolo]);
            ldsm4(af[1], &Ah[arow + 16][kk + acolo]);

            #pragma unroll
            for (int g = 0; g < 4; ++g) {
                unsigned bf[4];
                ldsm4(bf, &Bs[g * 32 + brow][kk + bcolo]);
                #pragma unroll
                for (int mt = 0; mt < 2; ++mt) {
                    mma16816(d[mt][g][0], af[mt], bf[0], bf[1]);
                    mma16816(d[mt][g][1], af[mt], bf[2], bf[3]);
                }
            }
        }

        // this warp is done reading slot scur (ldsm is synchronous)
        if (lane == 0) MBAR_ARRIVE(MB + scur * 16 + 8);

        const int kt = kc + 2;
        if (kt < KITER) {
            const int swr = kt % NSTAGE;
            const int r   = kt / NSTAGE;
            if (r >= 1) MBAR_WAIT(MB + swr * 16 + 8, (r - 1) & 1);  // slot free
            ISSUE_A(kt, swr);
            ISSUE_B(kt, swr);
            CP_MBAR_ARRIVE(MB + swr * 16);
        }
    }
    #undef ISSUE_A
    #undef ISSUE_B

    // ---------- epilogue: thread-local gate fusion ----------
    const int gid = lane >> 2;
    const int tig = lane & 3;
    const bool last = (t == SEQL - 1);

    #pragma unroll
    for (int mt = 0; mt < 2; ++mt) {
        #pragma unroll
        for (int rh = 0; rh < 2; ++rh) {
            int m = mb * 128 + warp_m + mt * 16 + gid + rh * 8;
            #pragma unroll
            for (int j = 0; j < 2; ++j) {
                int hcol = nb * 32 + hsl + j * 8 + tig * 2;

                // one 16B load: [hcol: i,f,g,o | hcol+1: i,f,g,o] fp16
                uint4 pk = *(const uint4*)(xph + ((size_t)m * 512 + hcol) * 4);
                __half2* hp = (__half2*)&pk;
                float2 if0 = __half22float2(hp[0]);
                float2 go0 = __half22float2(hp[1]);
                float2 if1 = __half22float2(hp[2]);
                float2 go1 = __half22float2(hp[3]);

                float gix = if0.x + d[mt][0][j][rh * 2];
                float giy = if1.x + d[mt][0][j][rh * 2 + 1];
                float gfx = if0.y + d[mt][1][j][rh * 2];
                float gfy = if1.y + d[mt][1][j][rh * 2 + 1];
                float ggx = go0.x + d[mt][2][j][rh * 2];
                float ggy = go1.x + d[mt][2][j][rh * 2 + 1];
                float gox = go0.y + d[mt][3][j][rh * 2];
                float goy = go1.y + d[mt][3][j][rh * 2 + 1];

                float2 cv = *(const float2*)(c_in + (size_t)m * HDIM + hcol);

                float ix = siga(gix), iy = siga(giy);
                float fx = siga(gfx), fy = siga(gfy);
                float gx = tanha(ggx), gy = tanha(ggy);
                float ox = siga(gox), oy = siga(goy);

                float cnx = fmaf(fx, cv.x, ix * gx);
                float cny = fmaf(fy, cv.y, iy * gy);
                float hnx = ox * tanha(cnx);
                float hny = oy * tanha(cny);

                *(float2*)(c_out + (size_t)m * HDIM + hcol) = make_float2(cnx, cny);

                __half2 vh;
                vh.x = __float2half_rn(hnx);
                vh.y = __float2half_rn(hny);
                *(__half2*)(h_out + (size_t)m * HDIM + hcol) = vh;

                if (last) {
                    *(float2*)(outh + (size_t)m * HDIM + hcol) = make_float2(hnx, hny);
                    if (outc)
                        *(float2*)(outc + (size_t)m * HDIM + hcol) = make_float2(cnx, cny);
                }
            }
        }
    }

    // ---- signal: this (t, mb, nb) slice complete ----
    __threadfence();
    __syncthreads();
    if (tid == 0) atomicAdd(cnt + mb, 1u);
}

// =====================================================================
extern "C" void kernel_launch(void* const* d_in, const int* in_sizes, int n_in,
                              void* d_out, int out_size) {
    const float* start_emb = (const float*)d_in[0];
    const float* h0        = (const float*)d_in[1];
    const float* c0        = (const float*)d_in[2];
    const float* w_ih      = (const float*)d_in[3];
    const float* w_hh      = (const float*)d_in[4];
    const float* b_ih      = (const float*)d_in[5];
    const float* b_hh      = (const float*)d_in[6];
    float* out = (float*)d_out;

    float* cbuf;
    __half *xph, *hb, *wp;
    unsigned* cnt;
    cudaGetSymbolAddress((void**)&xph,  g_xph);
    cudaGetSymbolAddress((void**)&cbuf, g_c);
    cudaGetSymbolAddress((void**)&hb,   g_h16);
    cudaGetSymbolAddress((void**)&wp,   g_wp);
    cudaGetSymbolAddress((void**)&cnt,  g_cnt);

    cudaFuncSetAttribute(lstm_mega, cudaFuncAttributeMaxDynamicSharedMemorySize, SMEM_STEP);

    cudaMemsetAsync(cnt, 0, 32 * sizeof(unsigned), 0);
    cudaMemcpyAsync(cbuf, c0, (size_t)NH * sizeof(float), cudaMemcpyDeviceToDevice, 0);

    prep_w_kernel<<<(GDIM * 64) / 256, 256>>>(w_hh, wp);
    prep_h_kernel<<<(NH / 8) / 256, 256>>>(h0, hb);

    dim3 grid_xp(HDIM / 32, BATCH / 64);
    xproj_kernel<<<grid_xp, XP_NT>>>(start_emb, w_ih, b_ih, b_hh, xph);

    const bool out_has_c = (out_size >= 2 * NH);
    float* outc = out_has_c ? (out + NH) : nullptr;

    dim3 grid_mega(512, SEQL);   // (tile: mb*16+nb, step)
    lstm_mega<<<grid_mega, 256, SMEM_STEP>>>(wp, xph, hb, cbuf, out, outc, cnt);
}

// round 16
// speedup vs baseline: 1.7440x; 1.0016x over previous
#include <cuda_runtime.h>
#include <cuda_fp16.h>
#include <cstdint>

// Problem constants (B=4096, E=512, H=512, SEQ=128)
#define BATCH 4096
#define EDIM  512
#define HDIM  512
#define GDIM  2048
#define SEQL  128
#define NH    (BATCH * HDIM)

// step pipeline config: K chunks of 64, 3 slots, mbarrier ring
#define KCHUNK   64
#define KITER    (HDIM / KCHUNK)       // 8
#define NSTAGE   3
#define ROWPITCH 72                    // halves per smem row (144B = 9x16B)
#define ARR_B    (128 * ROWPITCH * 2)  // 18432 B per array
#define STAGE_B  (2 * ARR_B)           // A + B = 36864 B
#define SMEM_STEP (NSTAGE * STAGE_B + 64)   // +64 for mbarriers

// ---------------- device scratch (no allocation allowed) ----------------
__device__ __half g_xph[BATCH * GDIM];           // 16 MB, [m][hcol][gate] fp16
__device__ float g_c[2][NH];                     // 16 MB
__device__ __half g_h16[2][NH];                  // 8 MB
__device__ __half g_wp[GDIM * HDIM];             // 2 MB, packed [nb=16][p=128][k=512]
__device__ unsigned g_cnt[32];                   // per-mb step completion counters

// ---------------- helpers ----------------
__device__ __forceinline__ float tanha(float x) {
    float y; asm("tanh.approx.f32 %0, %1;" : "=f"(y) : "f"(x)); return y;
}
__device__ __forceinline__ float siga(float x) {
    return fmaf(0.5f, tanha(0.5f * x), 0.5f);
}
__device__ __forceinline__ void ldsm4(unsigned r[4], const void* p) {
    unsigned a = (unsigned)__cvta_generic_to_shared(p);
    asm volatile("ldmatrix.sync.aligned.m8n8.x4.shared.b16 {%0,%1,%2,%3}, [%4];"
                 : "=r"(r[0]), "=r"(r[1]), "=r"(r[2]), "=r"(r[3]) : "r"(a));
}
__device__ __forceinline__ void mma16816(float d[4], const unsigned a[4],
                                         unsigned b0, unsigned b1) {
    asm volatile(
        "mma.sync.aligned.m16n8k16.row.col.f32.f16.f16.f32 "
        "{%0,%1,%2,%3}, {%4,%5,%6,%7}, {%8,%9}, {%0,%1,%2,%3};"
        : "+f"(d[0]), "+f"(d[1]), "+f"(d[2]), "+f"(d[3])
        : "r"(a[0]), "r"(a[1]), "r"(a[2]), "r"(a[3]), "r"(b0), "r"(b1));
}
__device__ __forceinline__ void cp16(uint32_t dst, const void* src) {
    asm volatile("cp.async.cg.shared.global [%0], [%1], 16;" :: "r"(dst), "l"(src) : "memory");
}

// ---------------- mbarrier ops ----------------
#define MBAR_INIT(a, n) \
    asm volatile("mbarrier.init.shared.b64 [%0], %1;" :: "r"(a), "r"(n) : "memory")
#define MBAR_ARRIVE(a) \
    asm volatile("mbarrier.arrive.shared.b64 _, [%0];" :: "r"(a) : "memory")
// .noinc: arrive-on fires at completion of this thread's prior cp.asyncs
// WITHOUT incrementing the pending count at issue — the init count (256)
// already accounts for these arrivals. (Non-.noinc here deadlocks: R14.)
#define CP_MBAR_ARRIVE(a) \
    asm volatile("cp.async.mbarrier.arrive.noinc.shared::cta.b64 [%0];" :: "r"(a) : "memory")
#define MBAR_WAIT(a, ph) do {                                                   \
    asm volatile(                                                               \
        "{\n\t.reg .pred P1;\n\t"                                               \
        "WL_%=:\n\t"                                                            \
        "mbarrier.try_wait.parity.acquire.cta.shared::cta.b64 P1, [%0], %1, 0x989680;\n\t" \
        "@P1 bra.uni WD_%=;\n\t"                                                \
        "bra.uni WL_%=;\n\t"                                                    \
        "WD_%=:\n\t}"                                                           \
        :: "r"(a), "r"(ph) : "memory");                                         \
} while (0)

// ---------------- prep: W_hh -> packed fp16 ----------------
__global__ void prep_w_kernel(const float* __restrict__ w, __half* __restrict__ wp) {
    int t = blockIdx.x * blockDim.x + threadIdx.x;
    int row = t >> 6;
    int k0  = (t & 63) * 8;
    int g = row >> 9, hcol = row & 511;
    int nb = hcol >> 5, hc = hcol & 31;
    int p = g * 32 + hc;
    const float* src = w + (size_t)row * 512 + k0;
    __half v[8];
    #pragma unroll
    for (int i = 0; i < 8; ++i) v[i] = __float2half_rn(src[i]);
    *(uint4*)(wp + (size_t)nb * 128 * 512 + (size_t)p * 512 + k0) = *(const uint4*)v;
}

// ---------------- prep: h0 -> fp16 ----------------
__global__ void prep_h_kernel(const float* __restrict__ h0, __half* __restrict__ h16) {
    int t = blockIdx.x * blockDim.x + threadIdx.x;
    size_t base = (size_t)t * 8;
    __half v[8];
    #pragma unroll
    for (int i = 0; i < 8; ++i) v[i] = __float2half_rn(h0[base + i]);
    *(uint4*)(h16 + base) = *(const uint4*)v;
}

// =====================================================================
//  x-projection (one-time, fp32 SIMT) -> fp16 gate-interleaved output
// =====================================================================
#define XP_NT 256
__device__ __forceinline__ unsigned long long pack2(float x, float y) {
    unsigned long long r;
    asm("mov.b64 %0, {%1, %2};" : "=l"(r) : "f"(x), "f"(y));
    return r;
}
__device__ __forceinline__ void fma2(unsigned long long& acc, unsigned long long a, unsigned long long b) {
    asm("fma.rn.f32x2 %0, %1, %2, %0;" : "+l"(acc) : "l"(a), "l"(b));
}
__device__ __forceinline__ float2 unpack2(unsigned long long v) {
    float2 f;
    asm("mov.b64 {%0, %1}, %2;" : "=f"(f.x), "=f"(f.y) : "l"(v));
    return f;
}

__global__ void __launch_bounds__(XP_NT)
xproj_kernel(const float* __restrict__ x, const float* __restrict__ w_ih,
             const float* __restrict__ b_ih, const float* __restrict__ b_hh,
             __half* __restrict__ xph) {
    __shared__ float As[64][36];
    __shared__ float Bs[32][130];
    const int m0 = blockIdx.y * 64, n0 = blockIdx.x * 32;
    const int tid = threadIdx.x, ty = tid >> 4, tx = tid & 15;
    unsigned long long acc[4][4];
    #pragma unroll
    for (int r = 0; r < 4; ++r)
        #pragma unroll
        for (int g = 0; g < 4; ++g) acc[r][g] = 0ull;

    for (int kc = 0; kc < 512; kc += 32) {
        #pragma unroll
        for (int p = 0; p < 2; ++p) {
            int q = tid + p * XP_NT, m = q >> 3, kq = q & 7;
            *(float4*)(&As[m][kq * 4]) = *(const float4*)(x + (size_t)(m0 + m) * 512 + kc + kq * 4);
        }
        #pragma unroll
        for (int p = 0; p < 4; ++p) {
            int q = tid + p * XP_NT, n = q >> 3, kq = q & 7;
            int g = n >> 5, c = n & 31;
            float4 v = *(const float4*)(w_ih + (size_t)(g * 512 + n0 + c) * 512 + kc + kq * 4);
            Bs[kq * 4 + 0][n] = v.x; Bs[kq * 4 + 1][n] = v.y;
            Bs[kq * 4 + 2][n] = v.z; Bs[kq * 4 + 3][n] = v.w;
        }
        __syncthreads();
        #pragma unroll
        for (int k = 0; k < 32; ++k) {
            unsigned long long a2[4], b2[4];
            #pragma unroll
            for (int r = 0; r < 4; ++r) { float a = As[ty * 4 + r][k]; a2[r] = pack2(a, a); }
            #pragma unroll
            for (int g = 0; g < 4; ++g)
                b2[g] = *(const unsigned long long*)(&Bs[k][g * 32 + tx * 2]);
            #pragma unroll
            for (int r = 0; r < 4; ++r)
                #pragma unroll
                for (int g = 0; g < 4; ++g) fma2(acc[r][g], a2[r], b2[g]);
        }
        __syncthreads();
    }
    const int hcol = n0 + tx * 2;
    #pragma unroll
    for (int r = 0; r < 4; ++r) {
        int b = m0 + ty * 4 + r;
        __half* dst = xph + ((size_t)b * 512 + hcol) * 4;
        #pragma unroll
        for (int g = 0; g < 4; ++g) {
            int j = g * 512 + hcol;
            float2 v = unpack2(acc[r][g]);
            v.x += b_ih[j] + b_hh[j];
            v.y += b_ih[j + 1] + b_hh[j + 1];
            dst[g]     = __float2half_rn(v.x);
            dst[4 + g] = __float2half_rn(v.y);
        }
    }
}

// =====================================================================
//  Persistent LSTM: one CTA per (step, mb, nb) tile (R10 geometry).
//  grid = (512, 128): blockIdx.x = mb*16 + nb, blockIdx.y = step.
//  Coarse per-mb dependency spin; 3-slot mbarrier ring (warp skew).
//  NEW: xproj epilogue data prefetched into the dead ring slot 2
//  (empty[2] parity-1 fires exactly once, after kc=5's readers drain),
//  signaled via a dedicated xp_full barrier — epilogue reads smem.
// =====================================================================
__global__ void __launch_bounds__(256, 2)
lstm_mega(const __half* __restrict__ wpk,
          const __half* __restrict__ xph,
          __half* __restrict__ hbase,
          float* __restrict__ cbase,
          float* __restrict__ outh,
          float* __restrict__ outc,
          unsigned* __restrict__ cnt) {
    extern __shared__ __align__(16) unsigned char smc[];
    const uint32_t sb = (uint32_t)__cvta_generic_to_shared(smc);
    const uint32_t MB = sb + NSTAGE * STAGE_B;    // [full,empty] x 3, then xp_full
    const uint32_t XPF = MB + 48;

    const int t    = blockIdx.y;
    const int nb   = blockIdx.x & 15;   // 32 hcols
    const int mb   = blockIdx.x >> 4;   // 128 batch rows
    const int tid  = threadIdx.x;
    const int lane = tid & 31;
    const int w    = tid >> 5;
    const int warp_m = (w >> 1) * 32;
    const int hsl    = (w & 1) * 16;
    const int gid = lane >> 2;
    const int tig = lane & 3;

    const __half* h_in  = hbase + (size_t)(t & 1) * NH;
    __half*       h_out = hbase + (size_t)((t + 1) & 1) * NH;
    const float*  c_in  = cbase + (size_t)(t & 1) * NH;
    float*        c_out = cbase + (size_t)((t + 1) & 1) * NH;

    const __half* Ag = h_in + (size_t)mb * 128 * 512;
    const __half* Bg = wpk + (size_t)nb * 128 * 512;

    // ---- mbarrier init ----
    if (tid == 0) {
        #pragma unroll
        for (int s = 0; s < NSTAGE; ++s) {
            MBAR_INIT(MB + s * 16, 256);       // full[s]: one .noinc arrival/thread
            MBAR_INIT(MB + s * 16 + 8, 8);     // empty[s]: one arrive per warp
        }
        MBAR_INIT(XPF, 256);                    // xproj prefetch complete
    }
    __syncthreads();

    // ---- cp.async stage issue, split A (h rows) / B (weights) ----
    #define ISSUE_A(KC, SLOT) do {                                             \
        uint32_t sb0_ = sb + (SLOT) * STAGE_B;                                 \
        _Pragma("unroll")                                                      \
        for (int i_ = 0; i_ < 4; ++i_) {                                       \
            int idx_ = tid + i_ * 256;                                         \
            int row_ = idx_ >> 3;                                              \
            int ch_  = idx_ & 7;                                               \
            cp16(sb0_ + row_ * (ROWPITCH * 2) + ch_ * 16,                      \
                 Ag + (size_t)row_ * 512 + (KC) * KCHUNK + ch_ * 8);           \
        }                                                                      \
    } while (0)
    #define ISSUE_B(KC, SLOT) do {                                             \
        uint32_t sb0_ = sb + (SLOT) * STAGE_B + ARR_B;                         \
        _Pragma("unroll")                                                      \
        for (int i_ = 0; i_ < 4; ++i_) {                                       \
            int idx_ = tid + i_ * 256;                                         \
            int row_ = idx_ >> 3;                                              \
            int ch_  = idx_ & 7;                                               \
            cp16(sb0_ + row_ * (ROWPITCH * 2) + ch_ * 16,                      \
                 Bg + (size_t)row_ * 512 + (KC) * KCHUNK + ch_ * 8);           \
        }                                                                      \
    } while (0)

    // B has no h dependency: fetch under the dependency wait.
    ISSUE_B(0, 0);
    ISSUE_B(1, 1);

    // ---- coarse wait: all 16 producers of (t-1, mb) ----
    if (t > 0) {
        if (tid == 0) {
            const unsigned target = 16u * (unsigned)t;
            volatile unsigned* p = cnt + mb;
            while (*p < target) __nanosleep(64);
            __threadfence();
        }
        __syncthreads();
    }

    ISSUE_A(0, 0); CP_MBAR_ARRIVE(MB + 0 * 16);   // full[0] <- B0,B1,A0 complete
    ISSUE_A(1, 1); CP_MBAR_ARRIVE(MB + 1 * 16);   // full[1] <- +A1 complete

    float d[2][4][2][4];
    #pragma unroll
    for (int a = 0; a < 2; ++a)
        #pragma unroll
        for (int b = 0; b < 4; ++b)
            #pragma unroll
            for (int c = 0; c < 2; ++c)
                #pragma unroll
                for (int e = 0; e < 4; ++e) d[a][b][c][e] = 0.0f;

    const int arow  = warp_m + (lane & 15);
    const int acolo = (lane >> 4) * 8;
    const int brow  = hsl + ((lane >> 4) << 3) + (lane & 7);
    const int bcolo = ((lane >> 3) & 1) * 8;

    #pragma unroll
    for (int kc = 0; kc < KITER; ++kc) {
        if (kc == 7) {
            // slot 2 is dead after its round-1 readers drain (kc=5): parity 1
            // fires exactly once. Prefetch this thread's 8 xproj pairs into
            // slot 2 (p-major layout: conflict-free 16B lanes).
            MBAR_WAIT(MB + 2 * 16 + 8, 1);
            #pragma unroll
            for (int p = 0; p < 8; ++p) {
                int mt = p >> 2, rh = (p >> 1) & 1, j = p & 1;
                int m_ = mb * 128 + warp_m + mt * 16 + gid + rh * 8;
                int hc_ = nb * 32 + hsl + j * 8 + tig * 2;
                cp16(sb + 2 * STAGE_B + p * 4096 + tid * 16,
                     xph + ((size_t)m_ * 512 + hc_) * 4);
            }
            CP_MBAR_ARRIVE(XPF);
        }

        const int scur = kc % NSTAGE;
        MBAR_WAIT(MB + scur * 16, (kc / NSTAGE) & 1);

        unsigned char* stg = smc + scur * STAGE_B;
        __half (*Ah)[ROWPITCH] = (__half(*)[ROWPITCH])(stg);
        __half (*Bs)[ROWPITCH] = (__half(*)[ROWPITCH])(stg + ARR_B);

        #pragma unroll
        for (int kk = 0; kk < KCHUNK; kk += 16) {
            unsigned af[2][4];
            ldsm4(af[0], &Ah[arow][kk + acolo]);
            ldsm4(af[1], &Ah[arow + 16][kk + acolo]);

            #pragma unroll
            for (int g = 0; g < 4; ++g) {
                unsigned bf[4];
                ldsm4(bf, &Bs[g * 32 + brow][kk + bcolo]);
                #pragma unroll
                for (int mt = 0; mt < 2; ++mt) {
                    mma16816(d[mt][g][0], af[mt], bf[0], bf[1]);
                    mma16816(d[mt][g][1], af[mt], bf[2], bf[3]);
                }
            }
        }

        // this warp is done reading slot scur (ldsm is synchronous)
        if (lane == 0) MBAR_ARRIVE(MB + scur * 16 + 8);

        const int kt = kc + 2;
        if (kt < KITER) {
            const int swr = kt % NSTAGE;
            const int r   = kt / NSTAGE;
            if (r >= 1) MBAR_WAIT(MB + swr * 16 + 8, (r - 1) & 1);  // slot free
            ISSUE_A(kt, swr);
            ISSUE_B(kt, swr);
            CP_MBAR_ARRIVE(MB + swr * 16);
        }
    }
    #undef ISSUE_A
    #undef ISSUE_B

    // ---------- epilogue: thread-local gate fusion, xproj from smem ----------
    const bool last = (t == SEQL - 1);
    MBAR_WAIT(XPF, 0);

    #pragma unroll
    for (int mt = 0; mt < 2; ++mt) {
        #pragma unroll
        for (int rh = 0; rh < 2; ++rh) {
            int m = mb * 128 + warp_m + mt * 16 + gid + rh * 8;
            #pragma unroll
            for (int j = 0; j < 2; ++j) {
                int p = mt * 4 + rh * 2 + j;
                int hcol = nb * 32 + hsl + j * 8 + tig * 2;

                // prefetched 16B: [hcol: i,f,g,o | hcol+1: i,f,g,o] fp16
                uint4 pk = *(const uint4*)(smc + 2 * STAGE_B + p * 4096 + tid * 16);
                __half2* hp = (__half2*)&pk;
                float2 if0 = __half22float2(hp[0]);
                float2 go0 = __half22float2(hp[1]);
                float2 if1 = __half22float2(hp[2]);
                float2 go1 = __half22float2(hp[3]);

                float gix = if0.x + d[mt][0][j][rh * 2];
                float giy = if1.x + d[mt][0][j][rh * 2 + 1];
                float gfx = if0.y + d[mt][1][j][rh * 2];
                float gfy = if1.y + d[mt][1][j][rh * 2 + 1];
                float ggx = go0.x + d[mt][2][j][rh * 2];
                float ggy = go1.x + d[mt][2][j][rh * 2 + 1];
                float gox = go0.y + d[mt][3][j][rh * 2];
                float goy = go1.y + d[mt][3][j][rh * 2 + 1];

                float2 cv = *(const float2*)(c_in + (size_t)m * HDIM + hcol);

                float ix = siga(gix), iy = siga(giy);
                float fx = siga(gfx), fy = siga(gfy);
                float gx = tanha(ggx), gy = tanha(ggy);
                float ox = siga(gox), oy = siga(goy);

                float cnx = fmaf(fx, cv.x, ix * gx);
                float cny = fmaf(fy, cv.y, iy * gy);
                float hnx = ox * tanha(cnx);
                float hny = oy * tanha(cny);

                *(float2*)(c_out + (size_t)m * HDIM + hcol) = make_float2(cnx, cny);

                __half2 vh;
                vh.x = __float2half_rn(hnx);
                vh.y = __float2half_rn(hny);
                *(__half2*)(h_out + (size_t)m * HDIM + hcol) = vh;

                if (last) {
                    *(float2*)(outh + (size_t)m * HDIM + hcol) = make_float2(hnx, hny);
                    if (outc)
                        *(float2*)(outc + (size_t)m * HDIM + hcol) = make_float2(cnx, cny);
                }
            }
        }
    }

    // ---- signal: this (t, mb, nb) slice complete ----
    __threadfence();
    __syncthreads();
    if (tid == 0) atomicAdd(cnt + mb, 1u);
}

// =====================================================================
extern "C" void kernel_launch(void* const* d_in, const int* in_sizes, int n_in,
                              void* d_out, int out_size) {
    const float* start_emb = (const float*)d_in[0];
    const float* h0        = (const float*)d_in[1];
    const float* c0        = (const float*)d_in[2];
    const float* w_ih      = (const float*)d_in[3];
    const float* w_hh      = (const float*)d_in[4];
    const float* b_ih      = (const float*)d_in[5];
    const float* b_hh      = (const float*)d_in[6];
    float* out = (float*)d_out;

    float* cbuf;
    __half *xph, *hb, *wp;
    unsigned* cnt;
    cudaGetSymbolAddress((void**)&xph,  g_xph);
    cudaGetSymbolAddress((void**)&cbuf, g_c);
    cudaGetSymbolAddress((void**)&hb,   g_h16);
    cudaGetSymbolAddress((void**)&wp,   g_wp);
    cudaGetSymbolAddress((void**)&cnt,  g_cnt);

    cudaFuncSetAttribute(lstm_mega, cudaFuncAttributeMaxDynamicSharedMemorySize, SMEM_STEP);

    cudaMemsetAsync(cnt, 0, 32 * sizeof(unsigned), 0);
    cudaMemcpyAsync(cbuf, c0, (size_t)NH * sizeof(float), cudaMemcpyDeviceToDevice, 0);

    prep_w_kernel<<<(GDIM * 64) / 256, 256>>>(w_hh, wp);
    prep_h_kernel<<<(NH / 8) / 256, 256>>>(h0, hb);

    dim3 grid_xp(HDIM / 32, BATCH / 64);
    xproj_kernel<<<grid_xp, XP_NT>>>(start_emb, w_ih, b_ih, b_hh, xph);

    const bool out_has_c = (out_size >= 2 * NH);
    float* outc = out_has_c ? (out + NH) : nullptr;

    dim3 grid_mega(512, SEQL);   // (tile: mb*16+nb, step)
    lstm_mega<<<grid_mega, 256, SMEM_STEP>>>(wp, xph, hb, cbuf, out, outc, cnt);
}

// round 17
// speedup vs baseline: 1.7647x; 1.0119x over previous
#include <cuda_runtime.h>
#include <cuda_fp16.h>
#include <cstdint>

// Problem constants (B=4096, E=512, H=512, SEQ=128)
#define BATCH 4096
#define EDIM  512
#define HDIM  512
#define GDIM  2048
#define SEQL  128
#define NH    (BATCH * HDIM)

// step pipeline config: K chunks of 64, 3 slots, mbarrier ring
#define KCHUNK   64
#define KITER    (HDIM / KCHUNK)       // 8
#define NSTAGE   3
#define ROWPITCH 72                    // halves per smem row (144B = 9x16B)
#define ARR_B    (128 * ROWPITCH * 2)  // 18432 B per array
#define STAGE_B  (2 * ARR_B)           // A + B = 36864 B
#define SMEM_STEP (NSTAGE * STAGE_B + 64)   // +64 for mbarriers

// ---------------- device scratch (no allocation allowed) ----------------
__device__ __half g_xph[BATCH * GDIM];           // 16 MB, [m][hcol][gate] fp16
__device__ float g_c[2][NH];                     // 16 MB
__device__ __half g_h16[2][NH];                  // 8 MB
__device__ __half g_wp[GDIM * HDIM];             // 2 MB, packed [nb=16][p=128][k=512]
__device__ unsigned g_cnt[32 * 8];               // per-(mb, kchunk) completion counters

// ---------------- helpers ----------------
__device__ __forceinline__ float tanha(float x) {
    float y; asm("tanh.approx.f32 %0, %1;" : "=f"(y) : "f"(x)); return y;
}
__device__ __forceinline__ float siga(float x) {
    return fmaf(0.5f, tanha(0.5f * x), 0.5f);
}
__device__ __forceinline__ void ldsm4(unsigned r[4], const void* p) {
    unsigned a = (unsigned)__cvta_generic_to_shared(p);
    asm volatile("ldmatrix.sync.aligned.m8n8.x4.shared.b16 {%0,%1,%2,%3}, [%4];"
                 : "=r"(r[0]), "=r"(r[1]), "=r"(r[2]), "=r"(r[3]) : "r"(a));
}
__device__ __forceinline__ void mma16816(float d[4], const unsigned a[4],
                                         unsigned b0, unsigned b1) {
    asm volatile(
        "mma.sync.aligned.m16n8k16.row.col.f32.f16.f16.f32 "
        "{%0,%1,%2,%3}, {%4,%5,%6,%7}, {%8,%9}, {%0,%1,%2,%3};"
        : "+f"(d[0]), "+f"(d[1]), "+f"(d[2]), "+f"(d[3])
        : "r"(a[0]), "r"(a[1]), "r"(a[2]), "r"(a[3]), "r"(b0), "r"(b1));
}
__device__ __forceinline__ void cp16(uint32_t dst, const void* src) {
    asm volatile("cp.async.cg.shared.global [%0], [%1], 16;" :: "r"(dst), "l"(src) : "memory");
}

// ---------------- mbarrier ops ----------------
#define MBAR_INIT(a, n) \
    asm volatile("mbarrier.init.shared.b64 [%0], %1;" :: "r"(a), "r"(n) : "memory")
#define MBAR_ARRIVE(a) \
    asm volatile("mbarrier.arrive.shared.b64 _, [%0];" :: "r"(a) : "memory")
// .noinc: arrive-on fires at completion of this thread's prior cp.asyncs
// WITHOUT incrementing the pending count at issue — the init count (256)
// already accounts for these arrivals. (Non-.noinc here deadlocks: R14.)
#define CP_MBAR_ARRIVE(a) \
    asm volatile("cp.async.mbarrier.arrive.noinc.shared::cta.b64 [%0];" :: "r"(a) : "memory")
#define MBAR_WAIT(a, ph) do {                                                   \
    asm volatile(                                                               \
        "{\n\t.reg .pred P1;\n\t"                                               \
        "WL_%=:\n\t"                                                            \
        "mbarrier.try_wait.parity.acquire.cta.shared::cta.b64 P1, [%0], %1, 0x989680;\n\t" \
        "@P1 bra.uni WD_%=;\n\t"                                                \
        "bra.uni WL_%=;\n\t"                                                    \
        "WD_%=:\n\t}"                                                           \
        :: "r"(a), "r"(ph) : "memory");                                         \
} while (0)

// ---------------- prep: W_hh -> packed fp16 ----------------
__global__ void prep_w_kernel(const float* __restrict__ w, __half* __restrict__ wp) {
    int t = blockIdx.x * blockDim.x + threadIdx.x;
    int row = t >> 6;
    int k0  = (t & 63) * 8;
    int g = row >> 9, hcol = row & 511;
    int nb = hcol >> 5, hc = hcol & 31;
    int p = g * 32 + hc;
    const float* src = w + (size_t)row * 512 + k0;
    __half v[8];
    #pragma unroll
    for (int i = 0; i < 8; ++i) v[i] = __float2half_rn(src[i]);
    *(uint4*)(wp + (size_t)nb * 128 * 512 + (size_t)p * 512 + k0) = *(const uint4*)v;
}

// ---------------- prep: h0 -> fp16 ----------------
__global__ void prep_h_kernel(const float* __restrict__ h0, __half* __restrict__ h16) {
    int t = blockIdx.x * blockDim.x + threadIdx.x;
    size_t base = (size_t)t * 8;
    __half v[8];
    #pragma unroll
    for (int i = 0; i < 8; ++i) v[i] = __float2half_rn(h0[base + i]);
    *(uint4*)(h16 + base) = *(const uint4*)v;
}

// =====================================================================
//  x-projection (one-time, fp32 SIMT) -> fp16 gate-interleaved output
// =====================================================================
#define XP_NT 256
__device__ __forceinline__ unsigned long long pack2(float x, float y) {
    unsigned long long r;
    asm("mov.b64 %0, {%1, %2};" : "=l"(r) : "f"(x), "f"(y));
    return r;
}
__device__ __forceinline__ void fma2(unsigned long long& acc, unsigned long long a, unsigned long long b) {
    asm("fma.rn.f32x2 %0, %1, %2, %0;" : "+l"(acc) : "l"(a), "l"(b));
}
__device__ __forceinline__ float2 unpack2(unsigned long long v) {
    float2 f;
    asm("mov.b64 {%0, %1}, %2;" : "=f"(f.x), "=f"(f.y) : "l"(v));
    return f;
}

__global__ void __launch_bounds__(XP_NT)
xproj_kernel(const float* __restrict__ x, const float* __restrict__ w_ih,
             const float* __restrict__ b_ih, const float* __restrict__ b_hh,
             __half* __restrict__ xph) {
    __shared__ float As[64][36];
    __shared__ float Bs[32][130];
    const int m0 = blockIdx.y * 64, n0 = blockIdx.x * 32;
    const int tid = threadIdx.x, ty = tid >> 4, tx = tid & 15;
    unsigned long long acc[4][4];
    #pragma unroll
    for (int r = 0; r < 4; ++r)
        #pragma unroll
        for (int g = 0; g < 4; ++g) acc[r][g] = 0ull;

    for (int kc = 0; kc < 512; kc += 32) {
        #pragma unroll
        for (int p = 0; p < 2; ++p) {
            int q = tid + p * XP_NT, m = q >> 3, kq = q & 7;
            *(float4*)(&As[m][kq * 4]) = *(const float4*)(x + (size_t)(m0 + m) * 512 + kc + kq * 4);
        }
        #pragma unroll
        for (int p = 0; p < 4; ++p) {
            int q = tid + p * XP_NT, n = q >> 3, kq = q & 7;
            int g = n >> 5, c = n & 31;
            float4 v = *(const float4*)(w_ih + (size_t)(g * 512 + n0 + c) * 512 + kc + kq * 4);
            Bs[kq * 4 + 0][n] = v.x; Bs[kq * 4 + 1][n] = v.y;
            Bs[kq * 4 + 2][n] = v.z; Bs[kq * 4 + 3][n] = v.w;
        }
        __syncthreads();
        #pragma unroll
        for (int k = 0; k < 32; ++k) {
            unsigned long long a2[4], b2[4];
            #pragma unroll
            for (int r = 0; r < 4; ++r) { float a = As[ty * 4 + r][k]; a2[r] = pack2(a, a); }
            #pragma unroll
            for (int g = 0; g < 4; ++g)
                b2[g] = *(const unsigned long long*)(&Bs[k][g * 32 + tx * 2]);
            #pragma unroll
            for (int r = 0; r < 4; ++r)
                #pragma unroll
                for (int g = 0; g < 4; ++g) fma2(acc[r][g], a2[r], b2[g]);
        }
        __syncthreads();
    }
    const int hcol = n0 + tx * 2;
    #pragma unroll
    for (int r = 0; r < 4; ++r) {
        int b = m0 + ty * 4 + r;
        __half* dst = xph + ((size_t)b * 512 + hcol) * 4;
        #pragma unroll
        for (int g = 0; g < 4; ++g) {
            int j = g * 512 + hcol;
            float2 v = unpack2(acc[r][g]);
            v.x += b_ih[j] + b_hh[j];
            v.y += b_ih[j + 1] + b_hh[j + 1];
            dst[g]     = __float2half_rn(v.x);
            dst[4 + g] = __float2half_rn(v.y);
        }
    }
}

// =====================================================================
//  Persistent LSTM: one CTA per (step, mb, nb) tile (R16 structure).
//  grid = (512, 128): blockIdx.x = mb*16 + nb, blockIdx.y = step.
//  Fine-grained per-K-chunk dependencies WITHOUT barriers: every thread
//  polls cnt[mb][kt] >= 2t with ld.acquire.gpu before issuing chunk kt's
//  A loads. No CTA-wide convergence anywhere in the mainloop.
// =====================================================================
__global__ void __launch_bounds__(256, 2)
lstm_mega(const __half* __restrict__ wpk,
          const __half* __restrict__ xph,
          __half* __restrict__ hbase,
          float* __restrict__ cbase,
          float* __restrict__ outh,
          float* __restrict__ outc,
          unsigned* __restrict__ cnt) {
    extern __shared__ __align__(16) unsigned char smc[];
    const uint32_t sb = (uint32_t)__cvta_generic_to_shared(smc);
    const uint32_t MB = sb + NSTAGE * STAGE_B;    // [full,empty] x 3, then xp_full
    const uint32_t XPF = MB + 48;

    const int t    = blockIdx.y;
    const int nb   = blockIdx.x & 15;   // 32 hcols
    const int mb   = blockIdx.x >> 4;   // 128 batch rows
    const int tid  = threadIdx.x;
    const int lane = tid & 31;
    const int w    = tid >> 5;
    const int warp_m = (w >> 1) * 32;
    const int hsl    = (w & 1) * 16;
    const int gid = lane >> 2;
    const int tig = lane & 3;

    const __half* h_in  = hbase + (size_t)(t & 1) * NH;
    __half*       h_out = hbase + (size_t)((t + 1) & 1) * NH;
    const float*  c_in  = cbase + (size_t)(t & 1) * NH;
    float*        c_out = cbase + (size_t)((t + 1) & 1) * NH;

    const __half* Ag = h_in + (size_t)mb * 128 * 512;
    const __half* Bg = wpk + (size_t)nb * 128 * 512;

    const unsigned dep_target = 2u * (unsigned)t;
    const unsigned* depc = cnt + mb * 8;

    // per-thread poll: chunk kt's A cols come from producers (t-1, mb, 2kt/2kt+1).
    // ld.acquire.gpu pairs with producer's __threadfence + atomicAdd (release).
    #define POLL(KT) do {                                                      \
        if (dep_target) {                                                      \
            unsigned v_;                                                       \
            const unsigned* p_ = depc + (KT);                                  \
            while (true) {                                                     \
                asm volatile("ld.acquire.gpu.global.u32 %0, [%1];"             \
                             : "=r"(v_) : "l"(p_));                            \
                if (v_ >= dep_target) break;                                   \
                __nanosleep(32);                                               \
            }                                                                  \
        }                                                                      \
    } while (0)

    // ---- mbarrier init ----
    if (tid == 0) {
        #pragma unroll
        for (int s = 0; s < NSTAGE; ++s) {
            MBAR_INIT(MB + s * 16, 256);       // full[s]: one .noinc arrival/thread
            MBAR_INIT(MB + s * 16 + 8, 8);     // empty[s]: one arrive per warp
        }
        MBAR_INIT(XPF, 256);                    // xproj prefetch complete
    }
    __syncthreads();

    // ---- cp.async stage issue, split A (h rows) / B (weights) ----
    #define ISSUE_A(KC, SLOT) do {                                             \
        uint32_t sb0_ = sb + (SLOT) * STAGE_B;                                 \
        _Pragma("unroll")                                                      \
        for (int i_ = 0; i_ < 4; ++i_) {                                       \
            int idx_ = tid + i_ * 256;                                         \
            int row_ = idx_ >> 3;                                              \
            int ch_  = idx_ & 7;                                               \
            cp16(sb0_ + row_ * (ROWPITCH * 2) + ch_ * 16,                      \
                 Ag + (size_t)row_ * 512 + (KC) * KCHUNK + ch_ * 8);           \
        }                                                                      \
    } while (0)
    #define ISSUE_B(KC, SLOT) do {                                             \
        uint32_t sb0_ = sb + (SLOT) * STAGE_B + ARR_B;                         \
        _Pragma("unroll")                                                      \
        for (int i_ = 0; i_ < 4; ++i_) {                                       \
            int idx_ = tid + i_ * 256;                                         \
            int row_ = idx_ >> 3;                                              \
            int ch_  = idx_ & 7;                                               \
            cp16(sb0_ + row_ * (ROWPITCH * 2) + ch_ * 16,                      \
                 Bg + (size_t)row_ * 512 + (KC) * KCHUNK + ch_ * 8);           \
        }                                                                      \
    } while (0)

    // B has no h dependency: issue while producers may still be running.
    ISSUE_B(0, 0);
    ISSUE_B(1, 1);

    // chunk 0/1 dependencies only (2 producers each), not all 16
    POLL(0);
    ISSUE_A(0, 0); CP_MBAR_ARRIVE(MB + 0 * 16);   // full[0] <- B0,B1,A0 complete
    POLL(1);
    ISSUE_A(1, 1); CP_MBAR_ARRIVE(MB + 1 * 16);   // full[1] <- +A1 complete

    float d[2][4][2][4];
    #pragma unroll
    for (int a = 0; a < 2; ++a)
        #pragma unroll
        for (int b = 0; b < 4; ++b)
            #pragma unroll
            for (int c = 0; c < 2; ++c)
                #pragma unroll
                for (int e = 0; e < 4; ++e) d[a][b][c][e] = 0.0f;

    const int arow  = warp_m + (lane & 15);
    const int acolo = (lane >> 4) * 8;
    const int brow  = hsl + ((lane >> 4) << 3) + (lane & 7);
    const int bcolo = ((lane >> 3) & 1) * 8;

    #pragma unroll
    for (int kc = 0; kc < KITER; ++kc) {
        if (kc == 7) {
            // slot 2 is dead after its round-1 readers drain (kc=5): parity 1
            // fires exactly once. Prefetch this thread's 8 xproj pairs into
            // slot 2 (p-major layout: conflict-free 16B lanes).
            MBAR_WAIT(MB + 2 * 16 + 8, 1);
            #pragma unroll
            for (int p = 0; p < 8; ++p) {
                int mt = p >> 2, rh = (p >> 1) & 1, j = p & 1;
                int m_ = mb * 128 + warp_m + mt * 16 + gid + rh * 8;
                int hc_ = nb * 32 + hsl + j * 8 + tig * 2;
                cp16(sb + 2 * STAGE_B + p * 4096 + tid * 16,
                     xph + ((size_t)m_ * 512 + hc_) * 4);
            }
            CP_MBAR_ARRIVE(XPF);
        }

        const int scur = kc % NSTAGE;
        MBAR_WAIT(MB + scur * 16, (kc / NSTAGE) & 1);

        unsigned char* stg = smc + scur * STAGE_B;
        __half (*Ah)[ROWPITCH] = (__half(*)[ROWPITCH])(stg);
        __half (*Bs)[ROWPITCH] = (__half(*)[ROWPITCH])(stg + ARR_B);

        #pragma unroll
        for (int kk = 0; kk < KCHUNK; kk += 16) {
            unsigned af[2][4];
            ldsm4(af[0], &Ah[arow][kk + acolo]);
            ldsm4(af[1], &Ah[arow + 16][kk + acolo]);

            #pragma unroll
            for (int g = 0; g < 4; ++g) {
                unsigned bf[4];
                ldsm4(bf, &Bs[g * 32 + brow][kk + bcolo]);
                #pragma unroll
                for (int mt = 0; mt < 2; ++mt) {
                    mma16816(d[mt][g][0], af[mt], bf[0], bf[1]);
                    mma16816(d[mt][g][1], af[mt], bf[2], bf[3]);
                }
            }
        }

        // this warp is done reading slot scur (ldsm is synchronous)
        if (lane == 0) MBAR_ARRIVE(MB + scur * 16 + 8);

        const int kt = kc + 2;
        if (kt < KITER) {
            const int swr = kt % NSTAGE;
            const int r   = kt / NSTAGE;
            if (r >= 1) MBAR_WAIT(MB + swr * 16 + 8, (r - 1) & 1);  // slot free
            ISSUE_B(kt, swr);       // dep-free; in flight during the poll
            POLL(kt);               // per-thread, no barrier: warp-skew preserved
            ISSUE_A(kt, swr);
            CP_MBAR_ARRIVE(MB + swr * 16);
        }
    }
    #undef ISSUE_A
    #undef ISSUE_B
    #undef POLL

    // ---------- epilogue: thread-local gate fusion, xproj from smem ----------
    const bool last = (t == SEQL - 1);
    MBAR_WAIT(XPF, 0);

    #pragma unroll
    for (int mt = 0; mt < 2; ++mt) {
        #pragma unroll
        for (int rh = 0; rh < 2; ++rh) {
            int m = mb * 128 + warp_m + mt * 16 + gid + rh * 8;
            #pragma unroll
            for (int j = 0; j < 2; ++j) {
                int p = mt * 4 + rh * 2 + j;
                int hcol = nb * 32 + hsl + j * 8 + tig * 2;

                // prefetched 16B: [hcol: i,f,g,o | hcol+1: i,f,g,o] fp16
                uint4 pk = *(const uint4*)(smc + 2 * STAGE_B + p * 4096 + tid * 16);
                __half2* hp = (__half2*)&pk;
                float2 if0 = __half22float2(hp[0]);
                float2 go0 = __half22float2(hp[1]);
                float2 if1 = __half22float2(hp[2]);
                float2 go1 = __half22float2(hp[3]);

                float gix = if0.x + d[mt][0][j][rh * 2];
                float giy = if1.x + d[mt][0][j][rh * 2 + 1];
                float gfx = if0.y + d[mt][1][j][rh * 2];
                float gfy = if1.y + d[mt][1][j][rh * 2 + 1];
                float ggx = go0.x + d[mt][2][j][rh * 2];
                float ggy = go1.x + d[mt][2][j][rh * 2 + 1];
                float gox = go0.y + d[mt][3][j][rh * 2];
                float goy = go1.y + d[mt][3][j][rh * 2 + 1];

                float2 cv = *(const float2*)(c_in + (size_t)m * HDIM + hcol);

                float ix = siga(gix), iy = siga(giy);
                float fx = siga(gfx), fy = siga(gfy);
                float gx = tanha(ggx), gy = tanha(ggy);
                float ox = siga(gox), oy = siga(goy);

                float cnx = fmaf(fx, cv.x, ix * gx);
                float cny = fmaf(fy, cv.y, iy * gy);
                float hnx = ox * tanha(cnx);
                float hny = oy * tanha(cny);

                *(float2*)(c_out + (size_t)m * HDIM + hcol) = make_float2(cnx, cny);

                __half2 vh;
                vh.x = __float2half_rn(hnx);
                vh.y = __float2half_rn(hny);
                *(__half2*)(h_out + (size_t)m * HDIM + hcol) = vh;

                if (last) {
                    *(float2*)(outh + (size_t)m * HDIM + hcol) = make_float2(hnx, hny);
                    if (outc)
                        *(float2*)(outc + (size_t)m * HDIM + hcol) = make_float2(cnx, cny);
                }
            }
        }
    }

    // ---- signal: this (t, mb, nb) slice complete (chunk kt = nb>>1) ----
    __threadfence();
    __syncthreads();
    if (tid == 0) atomicAdd(cnt + mb * 8 + (nb >> 1), 1u);
}

// =====================================================================
extern "C" void kernel_launch(void* const* d_in, const int* in_sizes, int n_in,
                              void* d_out, int out_size) {
    const float* start_emb = (const float*)d_in[0];
    const float* h0        = (const float*)d_in[1];
    const float* c0        = (const float*)d_in[2];
    const float* w_ih      = (const float*)d_in[3];
    const float* w_hh      = (const float*)d_in[4];
    const float* b_ih      = (const float*)d_in[5];
    const float* b_hh      = (const float*)d_in[6];
    float* out = (float*)d_out;

    float* cbuf;
    __half *xph, *hb, *wp;
    unsigned* cnt;
    cudaGetSymbolAddress((void**)&xph,  g_xph);
    cudaGetSymbolAddress((void**)&cbuf, g_c);
    cudaGetSymbolAddress((void**)&hb,   g_h16);
    cudaGetSymbolAddress((void**)&wp,   g_wp);
    cudaGetSymbolAddress((void**)&cnt,  g_cnt);

    cudaFuncSetAttribute(lstm_mega, cudaFuncAttributeMaxDynamicSharedMemorySize, SMEM_STEP);

    cudaMemsetAsync(cnt, 0, 32 * 8 * sizeof(unsigned), 0);
    cudaMemcpyAsync(cbuf, c0, (size_t)NH * sizeof(float), cudaMemcpyDeviceToDevice, 0);

    prep_w_kernel<<<(GDIM * 64) / 256, 256>>>(w_hh, wp);
    prep_h_kernel<<<(NH / 8) / 256, 256>>>(h0, hb);

    dim3 grid_xp(HDIM / 32, BATCH / 64);
    xproj_kernel<<<grid_xp, XP_NT>>>(start_emb, w_ih, b_ih, b_hh, xph);

    const bool out_has_c = (out_size >= 2 * NH);
    float* outc = out_has_c ? (out + NH) : nullptr;

    dim3 grid_mega(512, SEQL);   // (tile: mb*16+nb, step)
    lstm_mega<<<grid_mega, 256, SMEM_STEP>>>(wp, xph, hb, cbuf, out, outc, cnt);
}